// round 9
// baseline (speedup 1.0000x reference)
#include <cuda_runtime.h>
#include <cuda_fp16.h>
#include <math.h>
#include <stdint.h>

// Problem constants
#define BB 2
#define SS 2048
#define TT 2048
#define DIN 2048
#define DOUT 2048
#define HH 16
#define RD 64
#define HALF_RD 32
#define LL 512
#define HD 128
#define ROWS (BB*SS)          // 4096
#define QW (DOUT+HH*RD)       // 3072

// ---------------- device scratch (static; no allocations) ---------------------
__device__ __align__(128) __half g_x16  [ROWS*DIN];
__device__ __align__(128) __half g_wdkv16[LL*DIN];
__device__ __align__(128) __half g_wkr16 [HH*RD*DIN];
__device__ __align__(128) __half g_wq16  [QW*DIN];
__device__ __align__(128) __half g_wo16  [DIN*DOUT];
__device__ __align__(128) __half g_ckv16 [BB*SS*LL];
__device__ __align__(128) __half g_ckvT16[BB*LL*SS];
__device__ __align__(128) __half g_krope16[BB*SS*HH*RD];
__device__ __align__(128) __half g_q16   [BB*SS*QW];
__device__ __align__(128) __half g_qabs16[ROWS*HH*LL];
__device__ __align__(128) __half g_wukT16[LL*DOUT];
__device__ __align__(128) __half g_scores16[(long)BB*HH*SS*TT];
__device__ __align__(128) __half g_probs16 [(long)BB*HH*SS*TT];
__device__ __align__(128) float  g_ctxlat[ROWS*HH*LL];
__device__ __align__(128) __half g_ctx16 [ROWS*DOUT];

// ================= helpers =====================================================
__device__ __forceinline__ float f2tf(float x) {
    uint32_t u; asm("cvt.rna.tf32.f32 %0, %1;" : "=r"(u) : "f"(x));
    return __uint_as_float(u);
}
__device__ __forceinline__ uint32_t smem_u32(const void* p) {
    uint32_t a;
    asm("{ .reg .u64 t; cvta.to.shared.u64 t, %1; cvt.u32.u64 %0, t; }" : "=r"(a) : "l"(p));
    return a;
}
__device__ __forceinline__ void cp16(uint32_t dst, const void* src) {
    asm volatile("cp.async.cg.shared.global [%0], [%1], 16;" :: "r"(dst), "l"(src));
}
#define CP_COMMIT() asm volatile("cp.async.commit_group;" ::: "memory")
#define CP_WAIT2()  asm volatile("cp.async.wait_group 2;"  ::: "memory")
#define CP_WAIT0()  asm volatile("cp.async.wait_group 0;"  ::: "memory")

__device__ __forceinline__ void ldsm4(uint32_t* r, uint32_t addr) {
    asm volatile("ldmatrix.sync.aligned.m8n8.x4.shared.b16 {%0,%1,%2,%3}, [%4];"
                 : "=r"(r[0]), "=r"(r[1]), "=r"(r[2]), "=r"(r[3]) : "r"(addr));
}
__device__ __forceinline__ void mma_tf32(float* c, const uint32_t* a, const uint32_t* b) {
    asm volatile(
        "mma.sync.aligned.m16n8k8.row.col.f32.tf32.tf32.f32 "
        "{%0,%1,%2,%3}, {%4,%5,%6,%7}, {%8,%9}, {%0,%1,%2,%3};"
        : "+f"(c[0]), "+f"(c[1]), "+f"(c[2]), "+f"(c[3])
        : "r"(a[0]), "r"(a[1]), "r"(a[2]), "r"(a[3]), "r"(b[0]), "r"(b[1]));
}
__device__ __forceinline__ void mma_f16(float* c, const uint32_t* a, const uint32_t* b) {
    asm volatile(
        "mma.sync.aligned.m16n8k16.row.col.f32.f16.f16.f32 "
        "{%0,%1,%2,%3}, {%4,%5,%6,%7}, {%8,%9}, {%0,%1,%2,%3};"
        : "+f"(c[0]), "+f"(c[1]), "+f"(c[2]), "+f"(c[3])
        : "r"(a[0]), "r"(a[1]), "r"(a[2]), "r"(a[3]), "r"(b[0]), "r"(b[1]));
}

// ================= FP16 GEMM tile engine: 128x256, K-chunk 32 ==================
// acc += A[0..128,:K] @ B[0..256,:K]^T ; half operands, fp32 accum.
// pitch 40 halves; stage = A(128x40x2=10240B) + B(256x40x2=20480B) = 30720 B.
#define STGB 30720
#define GEMM_SMEM_H (4*STGB)     // 122880
#define GEMM_SMEM_F3 81920

__device__ __forceinline__ void gemm_tiles_h(
    const __half* __restrict__ A, const __half* __restrict__ B,
    int K, int lda, int ldb, float (*acc)[8][4], char* sm)
{
    const int tid  = threadIdx.x;
    const int lane = tid & 31;
    const int wid  = tid >> 5;
    const int wm   = wid >> 2;   // 0..1
    const int wn   = wid & 3;    // 0..3

    const uint32_t sbase = smem_u32(sm);

    const int aRow = wm * 64 + (lane & 7) + ((lane >> 3) & 1) * 8;
    const uint32_t aOff = (uint32_t)(aRow * 40 + ((lane >> 4) & 1) * 8) * 2;
    const int bRow = wn * 64 + (lane & 7) + ((lane >> 4) & 1) * 8;
    const uint32_t bOff = (uint32_t)(bRow * 40 + ((lane >> 3) & 1) * 8) * 2;

    auto issue = [&](int c) {
        const int k0 = c << 5;
        const uint32_t st = sbase + (uint32_t)(c & 3) * STGB;
        #pragma unroll
        for (int i = 0; i < 2; i++) {            // A: 512 cp16
            int op = tid + i * 256;
            int row = op >> 2, cc8 = (op & 3) * 8;
            cp16(st + (uint32_t)(row * 40 + cc8) * 2,
                 A + (long)row * lda + k0 + cc8);
        }
        #pragma unroll
        for (int i = 0; i < 4; i++) {            // B: 1024 cp16
            int op = tid + i * 256;
            int row = op >> 2, cc8 = (op & 3) * 8;
            cp16(st + 10240 + (uint32_t)(row * 40 + cc8) * 2,
                 B + (long)row * ldb + k0 + cc8);
        }
    };

    auto compute = [&](int c) {
        const uint32_t As = sbase + (uint32_t)(c & 3) * STGB;
        const uint32_t Bs = As + 10240;
        #pragma unroll
        for (int ks = 0; ks < 2; ks++) {
            uint32_t ah[4][4], bh[8][2];
            #pragma unroll
            for (int mt = 0; mt < 4; mt++)
                ldsm4(ah[mt], As + aOff + (uint32_t)(mt * 16 * 40 + ks * 16) * 2);
            #pragma unroll
            for (int np = 0; np < 4; np++) {
                uint32_t raw[4];
                ldsm4(raw, Bs + bOff + (uint32_t)(np * 16 * 40 + ks * 16) * 2);
                bh[np * 2][0] = raw[0]; bh[np * 2][1] = raw[1];
                bh[np * 2 + 1][0] = raw[2]; bh[np * 2 + 1][1] = raw[3];
            }
            #pragma unroll
            for (int mt = 0; mt < 4; mt++)
                #pragma unroll
                for (int nt = 0; nt < 8; nt++)
                    mma_f16(acc[mt][nt], ah[mt], bh[nt]);
        }
    };

    const int NC = K >> 5;
    if (0 < NC) issue(0); CP_COMMIT();
    if (1 < NC) issue(1); CP_COMMIT();
    if (2 < NC) issue(2); CP_COMMIT();
    for (int c = 0; c < NC; c++) {
        CP_WAIT2();
        __syncthreads();
        if (c + 3 < NC) issue(c + 3);
        CP_COMMIT();
        compute(c);
    }
    CP_WAIT0();
    __syncthreads();
}

// epilogue: OUTH=1 writes __half, else float
template<int OUTH>
__device__ __forceinline__ void gemm_epi(
    void* __restrict__ Cv, int ldc, int m0, int n0, float (*acc)[8][4])
{
    const int lane = threadIdx.x & 31;
    const int wid  = threadIdx.x >> 5;
    const int gid  = lane >> 2;
    const int tig  = lane & 3;
    const int wm   = wid >> 2;
    const int wn   = wid & 3;
    #pragma unroll
    for (int mt = 0; mt < 4; mt++) {
        #pragma unroll
        for (int nt = 0; nt < 8; nt++) {
            int r  = m0 + wm * 64 + mt * 16 + gid;
            int cc = n0 + wn * 64 + nt * 8 + tig * 2;
            if (OUTH) {
                __half* C = (__half*)Cv;
                *(__half2*)&C[(long)r * ldc + cc] =
                    __floats2half2_rn(acc[mt][nt][0], acc[mt][nt][1]);
                *(__half2*)&C[(long)(r + 8) * ldc + cc] =
                    __floats2half2_rn(acc[mt][nt][2], acc[mt][nt][3]);
            } else {
                float* C = (float*)Cv;
                float2 v0 = { acc[mt][nt][0], acc[mt][nt][1] };
                float2 v1 = { acc[mt][nt][2], acc[mt][nt][3] };
                *(float2*)&C[(long)r * ldc + cc]       = v0;
                *(float2*)&C[(long)(r + 8) * ldc + cc] = v1;
            }
        }
    }
}

#define ACC_INIT8(acc) { _Pragma("unroll") for (int _m = 0; _m < 4; _m++) \
    _Pragma("unroll") for (int _n = 0; _n < 8; _n++) \
    _Pragma("unroll") for (int _i = 0; _i < 4; _i++) acc[_m][_n][_i] = 0.0f; }
#define ACC_INIT4(acc) { _Pragma("unroll") for (int _m = 0; _m < 4; _m++) \
    _Pragma("unroll") for (int _n = 0; _n < 4; _n++) \
    _Pragma("unroll") for (int _i = 0; _i < 4; _i++) acc[_m][_n][_i] = 0.0f; }

// generic batched fp16 GEMM (tile 128x256); kclip limits K causally (256-grain)
template<int OUTH>
__global__ void __launch_bounds__(256, 1)
gemm_h(const __half* __restrict__ Ab, const __half* __restrict__ Bb, void* __restrict__ Cb,
       int K, int lda, int ldb, int ldc,
       int zInner, long sAo, long sAi, long sBo, long sBi, long sCo, long sCi,
       const int* offset_p, int kclip)
{
    extern __shared__ char smc[];
    const int z  = blockIdx.z;
    const int zo = z / zInner, zi = z % zInner;
    const int m0 = blockIdx.y * 128;
    const int n0 = blockIdx.x * 256;
    if (kclip) {
        int lim = m0 + 128 + *offset_p;
        lim = (lim + 255) & ~255;
        if (lim < K) K = lim;
    }
    float acc[4][8][4];
    ACC_INIT8(acc);
    gemm_tiles_h(Ab + zo * sAo + zi * sAi + (long)m0 * lda,
                 Bb + zo * sBo + zi * sBi + (long)n0 * ldb,
                 K, lda, ldb, acc, smc);
    if (OUTH)
        gemm_epi<1>((__half*)Cb + zo * sCo + zi * sCi, ldc, m0, n0, acc);
    else
        gemm_epi<0>((float*)Cb + zo * sCo + zi * sCi, ldc, m0, n0, acc);
}

// fused triple projection (half out); segs: ckv 2 | krope 4 | q 12 blocks of 256
__global__ void __launch_bounds__(256, 1)
gemm_proj3(const __half* __restrict__ x,
           const __half* __restrict__ Wdkv, const __half* __restrict__ Wkr,
           const __half* __restrict__ Wq,
           __half* __restrict__ ckv, __half* __restrict__ krope, __half* __restrict__ q)
{
    extern __shared__ char smc[];
    const int bx = blockIdx.x;
    const __half* B; __half* C; int ldc, n0;
    if (bx < 2)      { B = Wdkv; C = ckv;   ldc = LL;       n0 = bx * 256; }
    else if (bx < 6) { B = Wkr;  C = krope; ldc = HH * RD;  n0 = (bx - 2) * 256; }
    else             { B = Wq;   C = q;     ldc = QW;       n0 = (bx - 6) * 256; }
    const int m0 = blockIdx.y * 128;
    float acc[4][8][4];
    ACC_INIT8(acc);
    gemm_tiles_h(x + (long)m0 * DIN, B + (long)n0 * DIN, DIN, DIN, DIN, acc, smc);
    gemm_epi<1>(C, ldc, m0, n0, acc);
}

// fused scores: rope (K=64) + latent (K=512), causal block skip, half out
__global__ void __launch_bounds__(256, 1)
gemm_scores(const __half* __restrict__ q, const __half* __restrict__ krope,
            const __half* __restrict__ qabs, const __half* __restrict__ ckv,
            __half* __restrict__ scores, const int* __restrict__ offset_p)
{
    extern __shared__ char smc[];
    const int m0 = blockIdx.y * 128;
    const int n0 = blockIdx.x * 256;
    if (n0 > m0 + 127 + *offset_p) return;
    const int b = blockIdx.z >> 4;
    const int h = blockIdx.z & 15;

    float acc[4][8][4];
    ACC_INIT8(acc);

    const __half* A1 = q + (long)b * SS * QW + DOUT + h * RD + (long)m0 * QW;
    const __half* B1 = krope + (long)b * SS * (HH * RD) + h * RD + (long)n0 * (HH * RD);
    gemm_tiles_h(A1, B1, RD, QW, HH * RD, acc, smc);

    const __half* A2 = qabs + (long)b * SS * (HH * LL) + h * LL + (long)m0 * (HH * LL);
    const __half* B2 = ckv + (long)b * SS * LL + (long)n0 * LL;
    gemm_tiles_h(A2, B2, LL, HH * LL, LL, acc, smc);

    gemm_epi<1>(scores + (long)blockIdx.z * SS * TT, TT, m0, n0, acc);
}

// ================= FP32/tf32x3 engine for the ctx GEMM (precision-critical) ====
__device__ __forceinline__ void gemm_tiles_f3(
    const float* __restrict__ A, const float* __restrict__ B,
    int K, int lda, int ldb, float (*acc)[4][4], float* sm)
{
    const int tid  = threadIdx.x;
    const int lane = tid & 31;
    const int wid  = tid >> 5;
    const int wm   = wid >> 2;
    const int wn   = wid & 3;
    const uint32_t sbase = smem_u32(sm);

    const int r8   = lane & 7;
    const int aRow = wm * 64 + r8 + ((lane >> 3) & 1) * 8;
    const uint32_t aOff = (uint32_t)(aRow * 20 + ((lane >> 4) & 1) * 4) * 4;
    const int bRow = wn * 32 + r8 + ((lane >> 4) & 1) * 8;
    const uint32_t bOff = (uint32_t)(bRow * 20 + ((lane >> 3) & 1) * 4) * 4;

    const int crow = tid >> 2;
    const int cc4  = tid & 3;
    auto issue = [&](int c) {
        const int k0  = c << 4;
        const uint32_t st = sbase + (uint32_t)(c & 3) * 20480;
        #pragma unroll
        for (int i = 0; i < 2; i++) {
            int row = crow + i * 64;
            uint32_t d = st + (uint32_t)(row * 20 + cc4 * 4) * 4;
            cp16(d,          A + (long)row * lda + k0 + cc4 * 4);
            cp16(d + 10240,  B + (long)row * ldb + k0 + cc4 * 4);
        }
    };
    auto compute = [&](int c) {
        const uint32_t As = sbase + (uint32_t)(c & 3) * 20480;
        const uint32_t Bs = As + 10240;
        #pragma unroll
        for (int ks = 0; ks < 2; ks++) {
            uint32_t ah[4][4], bh[4][2], al[4][4], bl[4][2];
            #pragma unroll
            for (int mt = 0; mt < 4; mt++) {
                uint32_t raw[4];
                ldsm4(raw, As + aOff + (uint32_t)(mt * 16 * 20 + ks * 8) * 4);
                #pragma unroll
                for (int i = 0; i < 4; i++) {
                    float v = __uint_as_float(raw[i]);
                    float h = f2tf(v);
                    ah[mt][i] = __float_as_uint(h);
                    al[mt][i] = __float_as_uint(f2tf(v - h));
                }
            }
            #pragma unroll
            for (int ntp = 0; ntp < 2; ntp++) {
                uint32_t raw[4];
                ldsm4(raw, Bs + bOff + (uint32_t)(ntp * 16 * 20 + ks * 8) * 4);
                #pragma unroll
                for (int i = 0; i < 4; i++) {
                    int nt = ntp * 2 + (i >> 1), kk = i & 1;
                    float v = __uint_as_float(raw[i]);
                    float h = f2tf(v);
                    bh[nt][kk] = __float_as_uint(h);
                    bl[nt][kk] = __float_as_uint(f2tf(v - h));
                }
            }
            #pragma unroll
            for (int mt = 0; mt < 4; mt++)
                #pragma unroll
                for (int nt = 0; nt < 4; nt++) {
                    mma_tf32(acc[mt][nt], ah[mt], bh[nt]);
                    mma_tf32(acc[mt][nt], ah[mt], bl[nt]);
                    mma_tf32(acc[mt][nt], al[mt], bh[nt]);
                }
        }
    };
    const int NC = K >> 4;
    issue(0); CP_COMMIT();
    issue(1); CP_COMMIT();
    issue(2); CP_COMMIT();
    for (int c = 0; c < NC; c++) {
        CP_WAIT2();
        __syncthreads();
        if (c + 3 < NC) issue(c + 3);
        CP_COMMIT();
        compute(c);
    }
    CP_WAIT0();
    __syncthreads();
}

// narrow epilogue (128x128 tile) for tf32x3 ctx kernel
__device__ __forceinline__ void gemm_epi_h4(
    __half* __restrict__ C, int ldc, int m0, int n0, float (*acc)[4][4])
{
    const int lane = threadIdx.x & 31;
    const int wid  = threadIdx.x >> 5;
    const int gid  = lane >> 2;
    const int tig  = lane & 3;
    const int wm   = wid >> 2;
    const int wn   = wid & 3;
    #pragma unroll
    for (int mt = 0; mt < 4; mt++) {
        #pragma unroll
        for (int nt = 0; nt < 4; nt++) {
            int r  = m0 + wm * 64 + mt * 16 + gid;
            int cc = n0 + wn * 32 + nt * 8 + tig * 2;
            *(__half2*)&C[(long)r * ldc + cc] =
                __floats2half2_rn(acc[mt][nt][0], acc[mt][nt][1]);
            *(__half2*)&C[(long)(r + 8) * ldc + cc] =
                __floats2half2_rn(acc[mt][nt][2], acc[mt][nt][3]);
        }
    }
}

// ctx = ctxlat @ W_UV^T per head, tf32x3, half output
__global__ void __launch_bounds__(256, 1)
gemm_ctx3(const float* __restrict__ ctxlat, const float* __restrict__ Wuv,
          __half* __restrict__ ctx)
{
    extern __shared__ float smf[];
    const int h  = blockIdx.z;
    const int m0 = blockIdx.y * 128;
    float acc[4][4][4];
    ACC_INIT4(acc);
    gemm_tiles_f3(ctxlat + h * LL + (long)m0 * (HH * LL),
                  Wuv + (long)h * HD * LL,
                  LL, HH * LL, LL, acc, smf);
    gemm_epi_h4(ctx + h * HD, DOUT, m0, 0, acc);
}

// ================= small kernels ===============================================
__global__ void halfify_kernel(const float* __restrict__ in, __half* __restrict__ out, int n4)
{
    int i = blockIdx.x * blockDim.x + threadIdx.x;
    if (i >= n4) return;
    float4 v = ((const float4*)in)[i];
    __half2* o = (__half2*)out;
    o[i * 2]     = __floats2half2_rn(v.x, v.y);
    o[i * 2 + 1] = __floats2half2_rn(v.z, v.w);
}

__global__ void rmsnorm_kernel(__half* __restrict__ data, const float* __restrict__ w)
{
    const int row = blockIdx.x;
    __half* p = data + (long)row * LL;
    float ss = 0.0f;
    float vals[4];
    #pragma unroll
    for (int i = 0; i < 4; i++) {
        vals[i] = __half2float(p[threadIdx.x + i * 128]);
        ss += vals[i] * vals[i];
    }
    __shared__ float red[32];
    for (int o = 16; o; o >>= 1) ss += __shfl_xor_sync(0xffffffffu, ss, o);
    if ((threadIdx.x & 31) == 0) red[threadIdx.x >> 5] = ss;
    __syncthreads();
    if (threadIdx.x < 32) {
        float v = (threadIdx.x < 4) ? red[threadIdx.x] : 0.0f;
        for (int o = 16; o; o >>= 1) v += __shfl_xor_sync(0xffffffffu, v, o);
        if (threadIdx.x == 0) red[0] = v;
    }
    __syncthreads();
    float rstd = rsqrtf(red[0] / (float)LL + 1e-6f);
    #pragma unroll
    for (int i = 0; i < 4; i++)
        p[threadIdx.x + i * 128] = __float2half_rn(vals[i] * rstd * w[threadIdx.x + i * 128]);
}

__global__ void rope_kernel(__half* __restrict__ data, int ld, int colbase,
                            const int* __restrict__ offset_p)
{
    long idx = (long)blockIdx.x * blockDim.x + threadIdx.x;
    const long total = (long)ROWS * HH * HALF_RD;
    if (idx >= total) return;
    int  j   = (int)(idx % HALF_RD);
    int  h   = (int)((idx / HALF_RD) % HH);
    long row = idx / (HALF_RD * HH);
    int  s   = (int)(row % SS);
    float pos = (float)(s + *offset_p);
    float inv = expf(-(float)j * (logf(10000.0f) / 32.0f));
    float ang = pos * inv;
    float c  = cosf(ang);
    float si = sinf(ang);
    __half* p = data + row * (long)ld + colbase + h * RD;
    float x1 = __half2float(p[j]), x2 = __half2float(p[j + HALF_RD]);
    p[j]           = __float2half_rn(x1 * c - x2 * si);
    p[j + HALF_RD] = __float2half_rn(x2 * c + x1 * si);
}

// masked scaled softmax; half scores in, half probs out; zero-fill to 256-grain
__global__ void __launch_bounds__(256)
softmax_kernel(const __half* __restrict__ scores, __half* __restrict__ probs,
               const int* __restrict__ offset_p)
{
    const long row = blockIdx.x;            // (b*H+h)*S + s
    const int  s   = (int)(row % SS);
    const int  off = *offset_p;
    int valid = s + off + 1;
    if (valid > TT) valid = TT;
    int limit = ((s & ~127) + 128 + off + 255) & ~255;
    if (limit > TT) limit = TT;
    const __half* p = scores + row * (long)TT;
    __half* op = probs + row * (long)TT;
    const float scale = rsqrtf((float)(HD + RD));
    const int tid = threadIdx.x;
    const int e0 = tid * 8;

    float f[8];
    float m = -INFINITY;
    if (e0 < valid) {
        uint4 raw = *(const uint4*)(p + e0);
        const __half2* hp = (const __half2*)&raw;
        #pragma unroll
        for (int j = 0; j < 4; j++) {
            float2 v2 = __half22float2(hp[j]);
            f[j * 2]     = (e0 + j * 2 < valid)     ? v2.x * scale : -INFINITY;
            f[j * 2 + 1] = (e0 + j * 2 + 1 < valid) ? v2.y * scale : -INFINITY;
        }
        #pragma unroll
        for (int j = 0; j < 8; j++) m = fmaxf(m, f[j]);
    } else {
        #pragma unroll
        for (int j = 0; j < 8; j++) f[j] = -INFINITY;
    }

    __shared__ float red[32];
    for (int o = 16; o; o >>= 1) m = fmaxf(m, __shfl_xor_sync(0xffffffffu, m, o));
    if ((tid & 31) == 0) red[tid >> 5] = m;
    __syncthreads();
    if (tid < 32) {
        float t = (tid < 8) ? red[tid] : -INFINITY;
        for (int o = 16; o; o >>= 1) t = fmaxf(t, __shfl_xor_sync(0xffffffffu, t, o));
        if (tid == 0) red[0] = t;
    }
    __syncthreads();
    m = red[0];
    __syncthreads();

    float sum = 0.0f;
    #pragma unroll
    for (int j = 0; j < 8; j++) {
        float e = (f[j] == -INFINITY) ? 0.0f : expf(f[j] - m);
        f[j] = e;
        sum += e;
    }
    for (int o = 16; o; o >>= 1) sum += __shfl_xor_sync(0xffffffffu, sum, o);
    if ((tid & 31) == 0) red[tid >> 5] = sum;
    __syncthreads();
    if (tid < 32) {
        float t = (tid < 8) ? red[tid] : 0.0f;
        for (int o = 16; o; o >>= 1) t += __shfl_xor_sync(0xffffffffu, t, o);
        if (tid == 0) red[0] = t;
    }
    __syncthreads();
    float inv = 1.0f / red[0];

    if (e0 < limit) {
        uint4 outv;
        __half2* ho = (__half2*)&outv;
        #pragma unroll
        for (int j = 0; j < 4; j++)
            ho[j] = __floats2half2_rn(f[j * 2] * inv, f[j * 2 + 1] * inv);
        *(uint4*)(op + e0) = outv;
    }
}

// half->half 32x32 transpose, batched over z
__global__ void transpose_h(const __half* __restrict__ in, __half* __restrict__ out,
                            int R, int Cc, long sIn, long sOut)
{
    __shared__ __half t[32][33];
    const __half* ip = in + blockIdx.z * sIn;
    __half* op = out + blockIdx.z * sOut;
    const int c0 = blockIdx.x * 32, r0 = blockIdx.y * 32;
    for (int i = threadIdx.y; i < 32; i += 8)
        t[i][threadIdx.x] = ip[(long)(r0 + i) * Cc + c0 + threadIdx.x];
    __syncthreads();
    for (int i = threadIdx.y; i < 32; i += 8)
        op[(long)(c0 + i) * R + r0 + threadIdx.x] = t[threadIdx.x][i];
}

// float->half 32x32 transpose, batched over z (for W_UK)
__global__ void transpose_f2h(const float* __restrict__ in, __half* __restrict__ out,
                              int R, int Cc, long sIn, long sOut)
{
    __shared__ __half t[32][33];
    const float* ip = in + blockIdx.z * sIn;
    __half* op = out + blockIdx.z * sOut;
    const int c0 = blockIdx.x * 32, r0 = blockIdx.y * 32;
    for (int i = threadIdx.y; i < 32; i += 8)
        t[i][threadIdx.x] = __float2half_rn(ip[(long)(r0 + i) * Cc + c0 + threadIdx.x]);
    __syncthreads();
    for (int i = threadIdx.y; i < 32; i += 8)
        op[(long)(c0 + i) * R + r0 + threadIdx.x] = t[threadIdx.x][i];
}

// ================= host side ====================================================
template<typename T>
static T* sym_addr(const void* sym)
{
    void* p = nullptr;
    cudaGetSymbolAddress(&p, sym);
    return (T*)p;
}

extern "C" void kernel_launch(void* const* d_in, const int* in_sizes, int n_in,
                              void* d_out, int out_size)
{
    const float* x       = (const float*)d_in[0];
    const float* W_DKV   = (const float*)d_in[1];
    const float* W_KRope = (const float*)d_in[2];
    const float* W_Q     = (const float*)d_in[3];
    const float* W_UK    = (const float*)d_in[4];
    const float* W_UV    = (const float*)d_in[5];
    const float* W_O     = (const float*)d_in[6];
    const float* kvw     = (const float*)d_in[7];
    const int*   offset  = (const int*)d_in[8];
    float* out = (float*)d_out;

    static int s_init = 0;
    if (!s_init) {
        cudaFuncSetAttribute((const void*)gemm_h<0>, cudaFuncAttributeMaxDynamicSharedMemorySize, GEMM_SMEM_H);
        cudaFuncSetAttribute((const void*)gemm_h<1>, cudaFuncAttributeMaxDynamicSharedMemorySize, GEMM_SMEM_H);
        cudaFuncSetAttribute((const void*)gemm_proj3, cudaFuncAttributeMaxDynamicSharedMemorySize, GEMM_SMEM_H);
        cudaFuncSetAttribute((const void*)gemm_scores, cudaFuncAttributeMaxDynamicSharedMemorySize, GEMM_SMEM_H);
        cudaFuncSetAttribute((const void*)gemm_ctx3, cudaFuncAttributeMaxDynamicSharedMemorySize, GEMM_SMEM_F3);
        s_init = 1;
    }

    __half* x16    = sym_addr<__half>(g_x16);
    __half* wdkv16 = sym_addr<__half>(g_wdkv16);
    __half* wkr16  = sym_addr<__half>(g_wkr16);
    __half* wq16   = sym_addr<__half>(g_wq16);
    __half* wo16   = sym_addr<__half>(g_wo16);
    __half* ckv16  = sym_addr<__half>(g_ckv16);
    __half* ckvT16 = sym_addr<__half>(g_ckvT16);
    __half* krope16= sym_addr<__half>(g_krope16);
    __half* q16    = sym_addr<__half>(g_q16);
    __half* qabs16 = sym_addr<__half>(g_qabs16);
    __half* wukT16 = sym_addr<__half>(g_wukT16);
    __half* scores16 = sym_addr<__half>(g_scores16);
    __half* probs16  = sym_addr<__half>(g_probs16);
    float*  ctxlat = sym_addr<float>(g_ctxlat);
    __half* ctx16  = sym_addr<__half>(g_ctx16);

    // 0) half-round inputs
    halfify_kernel<<<(ROWS*DIN/4 + 255)/256, 256>>>(x, x16, ROWS*DIN/4);
    halfify_kernel<<<(LL*DIN/4 + 255)/256, 256>>>(W_DKV, wdkv16, LL*DIN/4);
    halfify_kernel<<<(HH*RD*DIN/4 + 255)/256, 256>>>(W_KRope, wkr16, HH*RD*DIN/4);
    halfify_kernel<<<(QW*DIN/4 + 255)/256, 256>>>(W_Q, wq16, QW*DIN/4);
    halfify_kernel<<<(DIN*DOUT/4 + 255)/256, 256>>>(W_O, wo16, DIN*DOUT/4);

    // 1-3) fused projections
    {
        dim3 grid(18, 32, 1);
        gemm_proj3<<<grid, 256, GEMM_SMEM_H>>>(x16, wdkv16, wkr16, wq16,
                                               ckv16, krope16, q16);
    }
    rmsnorm_kernel<<<ROWS, 128>>>(ckv16, kvw);
    {
        dim3 grid(LL / 32, SS / 32, BB), block(32, 8);
        transpose_h<<<grid, block>>>(ckv16, ckvT16, SS, LL,
                                     (long)SS * LL, (long)LL * SS);
    }
    {
        long total = (long)ROWS * HH * HALF_RD;
        rope_kernel<<<(int)((total + 255) / 256), 256>>>(krope16, HH * RD, 0, offset);
        rope_kernel<<<(int)((total + 255) / 256), 256>>>(q16, QW, DOUT, offset);
    }

    // W_UK^T per head (fp32 -> half)
    {
        dim3 grid(LL / 32, HD / 32, HH), block(32, 8);
        transpose_f2h<<<grid, block>>>(W_UK, wukT16, HD, LL,
                                       (long)HD * LL, (long)LL * HD);
    }

    // 4) q_abs (half out)
    {
        dim3 grid(LL / 256, ROWS / 128, HH);
        gemm_h<1><<<grid, 256, GEMM_SMEM_H>>>(q16, wukT16, qabs16,
            HD, QW, HD, HH * LL,
            HH, 0, HD, 0, (long)LL * HD, 0, LL, nullptr, 0);
    }

    // 5) fused scores (causal block skip), half out
    {
        dim3 grid(TT / 256, SS / 128, BB * HH);
        gemm_scores<<<grid, 256, GEMM_SMEM_H>>>(q16, krope16, qabs16, ckv16,
                                                scores16, offset);
    }

    // 6) softmax: half scores -> half probs
    softmax_kernel<<<BB * HH * SS, 256>>>(scores16, probs16, offset);

    // 7) ctx_lat = probs @ ckvT (K clipped causally), fp32 out
    {
        dim3 grid(LL / 256, SS / 128, BB * HH);
        gemm_h<0><<<grid, 256, GEMM_SMEM_H>>>(probs16, ckvT16, ctxlat,
            TT, TT, SS, HH * LL,
            HH, (long)HH * SS * TT, (long)SS * TT,
            (long)LL * SS, 0,
            (long)SS * HH * LL, LL, offset, 1);
    }

    // 8) ctx = ctxlat @ W_UV^T per head (tf32x3, half out)
    {
        dim3 grid(1, ROWS / 128, HH);
        gemm_ctx3<<<grid, 256, GEMM_SMEM_F3>>>(ctxlat, W_UV, ctx16);
    }

    // 9) out = ctx @ W_O^T (fp32 out)
    {
        dim3 grid(DIN / 256, ROWS / 128, 1);
        gemm_h<0><<<grid, 256, GEMM_SMEM_H>>>(ctx16, wo16, out,
            DOUT, DOUT, DOUT, DIN,
            1, 0, 0, 0, 0, 0, 0, nullptr, 0);
    }
}

// round 10
// speedup vs baseline: 1.1411x; 1.1411x over previous
#include <cuda_runtime.h>
#include <cuda_fp16.h>
#include <math.h>
#include <stdint.h>

// Problem constants
#define BB 2
#define SS 2048
#define TT 2048
#define DIN 2048
#define DOUT 2048
#define HH 16
#define RD 64
#define HALF_RD 32
#define LL 512
#define HD 128
#define ROWS (BB*SS)          // 4096
#define QW (DOUT+HH*RD)       // 3072

// ---------------- device scratch (static; no allocations) ---------------------
__device__ __align__(128) __half g_x16  [ROWS*DIN];
__device__ __align__(128) __half g_wdkv16[LL*DIN];
__device__ __align__(128) __half g_wkr16 [HH*RD*DIN];
__device__ __align__(128) __half g_wq16  [QW*DIN];
__device__ __align__(128) __half g_wo16  [DIN*DOUT];
__device__ __align__(128) __half g_ckv16 [BB*SS*LL];
__device__ __align__(128) __half g_ckvT16[BB*LL*SS];
__device__ __align__(128) __half g_krope16[BB*SS*HH*RD];
__device__ __align__(128) __half g_q16   [BB*SS*QW];
__device__ __align__(128) __half g_qabs16[ROWS*HH*LL];
__device__ __align__(128) __half g_wukT16[LL*DOUT];
__device__ __align__(128) __half g_scores16[(long)BB*HH*SS*TT];
__device__ __align__(128) __half g_probs16 [(long)BB*HH*SS*TT];
__device__ __align__(128) float  g_ctxlat[ROWS*HH*LL];
__device__ __align__(128) __half g_ctx16 [ROWS*DOUT];

// ================= helpers =====================================================
__device__ __forceinline__ float f2tf(float x) {
    uint32_t u; asm("cvt.rna.tf32.f32 %0, %1;" : "=r"(u) : "f"(x));
    return __uint_as_float(u);
}
__device__ __forceinline__ uint32_t smem_u32(const void* p) {
    uint32_t a;
    asm("{ .reg .u64 t; cvta.to.shared.u64 t, %1; cvt.u32.u64 %0, t; }" : "=r"(a) : "l"(p));
    return a;
}
__device__ __forceinline__ void cp16(uint32_t dst, const void* src) {
    asm volatile("cp.async.cg.shared.global [%0], [%1], 16;" :: "r"(dst), "l"(src));
}
#define CP_COMMIT() asm volatile("cp.async.commit_group;" ::: "memory")
#define CP_WAIT2()  asm volatile("cp.async.wait_group 2;"  ::: "memory")
#define CP_WAIT0()  asm volatile("cp.async.wait_group 0;"  ::: "memory")

__device__ __forceinline__ void ldsm4(uint32_t* r, uint32_t addr) {
    asm volatile("ldmatrix.sync.aligned.m8n8.x4.shared.b16 {%0,%1,%2,%3}, [%4];"
                 : "=r"(r[0]), "=r"(r[1]), "=r"(r[2]), "=r"(r[3]) : "r"(addr));
}
__device__ __forceinline__ void mma_tf32(float* c, const uint32_t* a, const uint32_t* b) {
    asm volatile(
        "mma.sync.aligned.m16n8k8.row.col.f32.tf32.tf32.f32 "
        "{%0,%1,%2,%3}, {%4,%5,%6,%7}, {%8,%9}, {%0,%1,%2,%3};"
        : "+f"(c[0]), "+f"(c[1]), "+f"(c[2]), "+f"(c[3])
        : "r"(a[0]), "r"(a[1]), "r"(a[2]), "r"(a[3]), "r"(b[0]), "r"(b[1]));
}
__device__ __forceinline__ void mma_f16(float* c, const uint32_t* a, const uint32_t* b) {
    asm volatile(
        "mma.sync.aligned.m16n8k16.row.col.f32.f16.f16.f32 "
        "{%0,%1,%2,%3}, {%4,%5,%6,%7}, {%8,%9}, {%0,%1,%2,%3};"
        : "+f"(c[0]), "+f"(c[1]), "+f"(c[2]), "+f"(c[3])
        : "r"(a[0]), "r"(a[1]), "r"(a[2]), "r"(a[3]), "r"(b[0]), "r"(b[1]));
}

#define GEMM_SMEM 81920

// ================= FP16 GEMM tile engine: 128x128, K-chunk 32 ==================
// acc += A[0..128,:K] @ B[0..128,:K]^T ; half operands, fp32 accum.
// pitch 40 halves (80B) per row; stage = A(5120h)+B(5120h) = 20480 B. 4 stages.
__device__ __forceinline__ void gemm_tiles_h(
    const __half* __restrict__ A, const __half* __restrict__ B,
    int K, int lda, int ldb, float (*acc)[4][4], char* sm)
{
    const int tid  = threadIdx.x;
    const int lane = tid & 31;
    const int wid  = tid >> 5;
    const int wm   = wid >> 2;
    const int wn   = wid & 3;

    const uint32_t sbase = smem_u32(sm);

    const int aRow = wm * 64 + (lane & 7) + ((lane >> 3) & 1) * 8;
    const uint32_t aOff = (uint32_t)(aRow * 40 + ((lane >> 4) & 1) * 8) * 2;
    const int bRow = wn * 32 + (lane & 7) + ((lane >> 4) & 1) * 8;
    const uint32_t bOff = (uint32_t)(bRow * 40 + ((lane >> 3) & 1) * 8) * 2;

    const int crow = tid >> 2;          // 0..63
    const int cc   = (tid & 3) * 8;     // half offset 0,8,16,24
    auto issue = [&](int c) {
        const int k0 = c << 5;
        const uint32_t st = sbase + (uint32_t)(c & 3) * 20480;
        #pragma unroll
        for (int i = 0; i < 2; i++) {
            int row = crow + i * 64;
            uint32_t d = st + (uint32_t)(row * 40 + cc) * 2;
            cp16(d,             A + (long)row * lda + k0 + cc);
            cp16(d + 10240,     B + (long)row * ldb + k0 + cc);
        }
    };

    auto compute = [&](int c) {
        const uint32_t As = sbase + (uint32_t)(c & 3) * 20480;
        const uint32_t Bs = As + 10240;
        #pragma unroll
        for (int ks = 0; ks < 2; ks++) {
            uint32_t ah[4][4], bh[4][2];
            #pragma unroll
            for (int mt = 0; mt < 4; mt++)
                ldsm4(ah[mt], As + aOff + (uint32_t)(mt * 16 * 40 + ks * 16) * 2);
            #pragma unroll
            for (int np = 0; np < 2; np++) {
                uint32_t raw[4];
                ldsm4(raw, Bs + bOff + (uint32_t)(np * 16 * 40 + ks * 16) * 2);
                bh[np * 2][0] = raw[0]; bh[np * 2][1] = raw[1];
                bh[np * 2 + 1][0] = raw[2]; bh[np * 2 + 1][1] = raw[3];
            }
            #pragma unroll
            for (int mt = 0; mt < 4; mt++)
                #pragma unroll
                for (int nt = 0; nt < 4; nt++)
                    mma_f16(acc[mt][nt], ah[mt], bh[nt]);
        }
    };

    const int NC = K >> 5;
    if (0 < NC) issue(0); CP_COMMIT();
    if (1 < NC) issue(1); CP_COMMIT();
    if (2 < NC) issue(2); CP_COMMIT();
    for (int c = 0; c < NC; c++) {
        CP_WAIT2();
        __syncthreads();
        if (c + 3 < NC) issue(c + 3);
        CP_COMMIT();
        compute(c);
    }
    CP_WAIT0();
    __syncthreads();
}

// epilogue: OUTH=1 writes __half, else float
template<int OUTH>
__device__ __forceinline__ void gemm_epi(
    void* __restrict__ Cv, int ldc, int m0, int n0, float (*acc)[4][4])
{
    const int lane = threadIdx.x & 31;
    const int wid  = threadIdx.x >> 5;
    const int gid  = lane >> 2;
    const int tig  = lane & 3;
    const int wm   = wid >> 2;
    const int wn   = wid & 3;
    #pragma unroll
    for (int mt = 0; mt < 4; mt++) {
        #pragma unroll
        for (int nt = 0; nt < 4; nt++) {
            int r  = m0 + wm * 64 + mt * 16 + gid;
            int cc = n0 + wn * 32 + nt * 8 + tig * 2;
            if (OUTH) {
                __half* C = (__half*)Cv;
                *(__half2*)&C[(long)r * ldc + cc] =
                    __floats2half2_rn(acc[mt][nt][0], acc[mt][nt][1]);
                *(__half2*)&C[(long)(r + 8) * ldc + cc] =
                    __floats2half2_rn(acc[mt][nt][2], acc[mt][nt][3]);
            } else {
                float* C = (float*)Cv;
                float2 v0 = { acc[mt][nt][0], acc[mt][nt][1] };
                float2 v1 = { acc[mt][nt][2], acc[mt][nt][3] };
                *(float2*)&C[(long)r * ldc + cc]       = v0;
                *(float2*)&C[(long)(r + 8) * ldc + cc] = v1;
            }
        }
    }
}

#define ACC_INIT(acc) { _Pragma("unroll") for (int _m = 0; _m < 4; _m++) \
    _Pragma("unroll") for (int _n = 0; _n < 4; _n++) \
    _Pragma("unroll") for (int _i = 0; _i < 4; _i++) acc[_m][_n][_i] = 0.0f; }

// generic batched fp16 GEMM; kclip limits K causally (128-grain)
template<int OUTH>
__global__ void __launch_bounds__(256, 2)
gemm_h(const __half* __restrict__ Ab, const __half* __restrict__ Bb, void* __restrict__ Cb,
       int K, int lda, int ldb, int ldc,
       int zInner, long sAo, long sAi, long sBo, long sBi, long sCo, long sCi,
       const int* offset_p, int kclip)
{
    extern __shared__ char smc[];
    const int z  = blockIdx.z;
    const int zo = z / zInner, zi = z % zInner;
    const int m0 = blockIdx.y * 128;
    const int n0 = blockIdx.x * 128;
    if (kclip) {
        int lim = m0 + 128 + *offset_p;
        lim = (lim + 127) & ~127;
        if (lim < K) K = lim;
    }
    float acc[4][4][4];
    ACC_INIT(acc);
    gemm_tiles_h(Ab + zo * sAo + zi * sAi + (long)m0 * lda,
                 Bb + zo * sBo + zi * sBi + (long)n0 * ldb,
                 K, lda, ldb, acc, smc);
    if (OUTH)
        gemm_epi<1>((__half*)Cb + zo * sCo + zi * sCi, ldc, m0, n0, acc);
    else
        gemm_epi<0>((float*)Cb + zo * sCo + zi * sCi, ldc, m0, n0, acc);
}

// fused triple projection (half out): ckv 4 | krope 8 | q 24 blocks of 128
__global__ void __launch_bounds__(256, 2)
gemm_proj3(const __half* __restrict__ x,
           const __half* __restrict__ Wdkv, const __half* __restrict__ Wkr,
           const __half* __restrict__ Wq,
           __half* __restrict__ ckv, __half* __restrict__ krope, __half* __restrict__ q)
{
    extern __shared__ char smc[];
    const int bx = blockIdx.x;
    const __half* B; __half* C; int ldc, n0;
    if (bx < 4)       { B = Wdkv; C = ckv;   ldc = LL;       n0 = bx * 128; }
    else if (bx < 12) { B = Wkr;  C = krope; ldc = HH * RD;  n0 = (bx - 4) * 128; }
    else              { B = Wq;   C = q;     ldc = QW;       n0 = (bx - 12) * 128; }
    const int m0 = blockIdx.y * 128;
    float acc[4][4][4];
    ACC_INIT(acc);
    gemm_tiles_h(x + (long)m0 * DIN, B + (long)n0 * DIN, DIN, DIN, DIN, acc, smc);
    gemm_epi<1>(C, ldc, m0, n0, acc);
}

// fused scores: rope (K=64) + latent (K=512), causal block skip, half out
__global__ void __launch_bounds__(256, 2)
gemm_scores(const __half* __restrict__ q, const __half* __restrict__ krope,
            const __half* __restrict__ qabs, const __half* __restrict__ ckv,
            __half* __restrict__ scores, const int* __restrict__ offset_p)
{
    extern __shared__ char smc[];
    const int m0 = blockIdx.y * 128;
    const int n0 = blockIdx.x * 128;
    if (n0 > m0 + 127 + *offset_p) return;
    const int b = blockIdx.z >> 4;
    const int h = blockIdx.z & 15;

    float acc[4][4][4];
    ACC_INIT(acc);

    const __half* A1 = q + (long)b * SS * QW + DOUT + h * RD + (long)m0 * QW;
    const __half* B1 = krope + (long)b * SS * (HH * RD) + h * RD + (long)n0 * (HH * RD);
    gemm_tiles_h(A1, B1, RD, QW, HH * RD, acc, smc);

    const __half* A2 = qabs + (long)b * SS * (HH * LL) + h * LL + (long)m0 * (HH * LL);
    const __half* B2 = ckv + (long)b * SS * LL + (long)n0 * LL;
    gemm_tiles_h(A2, B2, LL, HH * LL, LL, acc, smc);

    gemm_epi<1>(scores + (long)blockIdx.z * SS * TT, TT, m0, n0, acc);
}

// ================= FP32/tf32x3 engine for the ctx GEMM (precision-critical) ====
__device__ __forceinline__ void gemm_tiles_f3(
    const float* __restrict__ A, const float* __restrict__ B,
    int K, int lda, int ldb, float (*acc)[4][4], float* sm)
{
    const int tid  = threadIdx.x;
    const int lane = tid & 31;
    const int wid  = tid >> 5;
    const int wm   = wid >> 2;
    const int wn   = wid & 3;
    const uint32_t sbase = smem_u32(sm);

    const int r8   = lane & 7;
    const int aRow = wm * 64 + r8 + ((lane >> 3) & 1) * 8;
    const uint32_t aOff = (uint32_t)(aRow * 20 + ((lane >> 4) & 1) * 4) * 4;
    const int bRow = wn * 32 + r8 + ((lane >> 4) & 1) * 8;
    const uint32_t bOff = (uint32_t)(bRow * 20 + ((lane >> 3) & 1) * 4) * 4;

    const int crow = tid >> 2;
    const int cc4  = tid & 3;
    auto issue = [&](int c) {
        const int k0  = c << 4;
        const uint32_t st = sbase + (uint32_t)(c & 3) * 20480;
        #pragma unroll
        for (int i = 0; i < 2; i++) {
            int row = crow + i * 64;
            uint32_t d = st + (uint32_t)(row * 20 + cc4 * 4) * 4;
            cp16(d,          A + (long)row * lda + k0 + cc4 * 4);
            cp16(d + 10240,  B + (long)row * ldb + k0 + cc4 * 4);
        }
    };
    auto compute = [&](int c) {
        const uint32_t As = sbase + (uint32_t)(c & 3) * 20480;
        const uint32_t Bs = As + 10240;
        #pragma unroll
        for (int ks = 0; ks < 2; ks++) {
            uint32_t ah[4][4], bh[4][2], al[4][4], bl[4][2];
            #pragma unroll
            for (int mt = 0; mt < 4; mt++) {
                uint32_t raw[4];
                ldsm4(raw, As + aOff + (uint32_t)(mt * 16 * 20 + ks * 8) * 4);
                #pragma unroll
                for (int i = 0; i < 4; i++) {
                    float v = __uint_as_float(raw[i]);
                    float h = f2tf(v);
                    ah[mt][i] = __float_as_uint(h);
                    al[mt][i] = __float_as_uint(f2tf(v - h));
                }
            }
            #pragma unroll
            for (int ntp = 0; ntp < 2; ntp++) {
                uint32_t raw[4];
                ldsm4(raw, Bs + bOff + (uint32_t)(ntp * 16 * 20 + ks * 8) * 4);
                #pragma unroll
                for (int i = 0; i < 4; i++) {
                    int nt = ntp * 2 + (i >> 1), kk = i & 1;
                    float v = __uint_as_float(raw[i]);
                    float h = f2tf(v);
                    bh[nt][kk] = __float_as_uint(h);
                    bl[nt][kk] = __float_as_uint(f2tf(v - h));
                }
            }
            #pragma unroll
            for (int mt = 0; mt < 4; mt++)
                #pragma unroll
                for (int nt = 0; nt < 4; nt++) {
                    mma_tf32(acc[mt][nt], ah[mt], bh[nt]);
                    mma_tf32(acc[mt][nt], ah[mt], bl[nt]);
                    mma_tf32(acc[mt][nt], al[mt], bh[nt]);
                }
        }
    };
    const int NC = K >> 4;
    issue(0); CP_COMMIT();
    issue(1); CP_COMMIT();
    issue(2); CP_COMMIT();
    for (int c = 0; c < NC; c++) {
        CP_WAIT2();
        __syncthreads();
        if (c + 3 < NC) issue(c + 3);
        CP_COMMIT();
        compute(c);
    }
    CP_WAIT0();
    __syncthreads();
}

// ctx = ctxlat @ W_UV^T per head, tf32x3, half output
__global__ void __launch_bounds__(256, 1)
gemm_ctx3(const float* __restrict__ ctxlat, const float* __restrict__ Wuv,
          __half* __restrict__ ctx)
{
    extern __shared__ float smf[];
    const int h  = blockIdx.z;
    const int m0 = blockIdx.y * 128;
    float acc[4][4][4];
    ACC_INIT(acc);
    gemm_tiles_f3(ctxlat + h * LL + (long)m0 * (HH * LL),
                  Wuv + (long)h * HD * LL,
                  LL, HH * LL, LL, acc, smf);
    // half epilogue on 128x128 tile
    const int lane = threadIdx.x & 31;
    const int wid  = threadIdx.x >> 5;
    const int gid  = lane >> 2;
    const int tig  = lane & 3;
    const int wm   = wid >> 2;
    const int wn   = wid & 3;
    __half* C = ctx + h * HD;
    #pragma unroll
    for (int mt = 0; mt < 4; mt++) {
        #pragma unroll
        for (int nt = 0; nt < 4; nt++) {
            int r  = m0 + wm * 64 + mt * 16 + gid;
            int cc = wn * 32 + nt * 8 + tig * 2;
            *(__half2*)&C[(long)r * DOUT + cc] =
                __floats2half2_rn(acc[mt][nt][0], acc[mt][nt][1]);
            *(__half2*)&C[(long)(r + 8) * DOUT + cc] =
                __floats2half2_rn(acc[mt][nt][2], acc[mt][nt][3]);
        }
    }
}

// ================= small kernels ===============================================
__global__ void halfify_kernel(const float* __restrict__ in, __half* __restrict__ out, int n4)
{
    int i = blockIdx.x * blockDim.x + threadIdx.x;
    if (i >= n4) return;
    float4 v = ((const float4*)in)[i];
    __half2* o = (__half2*)out;
    o[i * 2]     = __floats2half2_rn(v.x, v.y);
    o[i * 2 + 1] = __floats2half2_rn(v.z, v.w);
}

__global__ void rmsnorm_kernel(__half* __restrict__ data, const float* __restrict__ w)
{
    const int row = blockIdx.x;
    __half* p = data + (long)row * LL;
    float ss = 0.0f;
    float vals[4];
    #pragma unroll
    for (int i = 0; i < 4; i++) {
        vals[i] = __half2float(p[threadIdx.x + i * 128]);
        ss += vals[i] * vals[i];
    }
    __shared__ float red[32];
    for (int o = 16; o; o >>= 1) ss += __shfl_xor_sync(0xffffffffu, ss, o);
    if ((threadIdx.x & 31) == 0) red[threadIdx.x >> 5] = ss;
    __syncthreads();
    if (threadIdx.x < 32) {
        float v = (threadIdx.x < 4) ? red[threadIdx.x] : 0.0f;
        for (int o = 16; o; o >>= 1) v += __shfl_xor_sync(0xffffffffu, v, o);
        if (threadIdx.x == 0) red[0] = v;
    }
    __syncthreads();
    float rstd = rsqrtf(red[0] / (float)LL + 1e-6f);
    #pragma unroll
    for (int i = 0; i < 4; i++)
        p[threadIdx.x + i * 128] = __float2half_rn(vals[i] * rstd * w[threadIdx.x + i * 128]);
}

__global__ void rope_kernel(__half* __restrict__ data, int ld, int colbase,
                            const int* __restrict__ offset_p)
{
    long idx = (long)blockIdx.x * blockDim.x + threadIdx.x;
    const long total = (long)ROWS * HH * HALF_RD;
    if (idx >= total) return;
    int  j   = (int)(idx % HALF_RD);
    int  h   = (int)((idx / HALF_RD) % HH);
    long row = idx / (HALF_RD * HH);
    int  s   = (int)(row % SS);
    float pos = (float)(s + *offset_p);
    float inv = expf(-(float)j * (logf(10000.0f) / 32.0f));
    float ang = pos * inv;
    float c  = cosf(ang);
    float si = sinf(ang);
    __half* p = data + row * (long)ld + colbase + h * RD;
    float x1 = __half2float(p[j]), x2 = __half2float(p[j + HALF_RD]);
    p[j]           = __float2half_rn(x1 * c - x2 * si);
    p[j + HALF_RD] = __float2half_rn(x2 * c + x1 * si);
}

// masked scaled softmax; half scores in, half probs out; zero-fill to 128-grain
__global__ void __launch_bounds__(256)
softmax_kernel(const __half* __restrict__ scores, __half* __restrict__ probs,
               const int* __restrict__ offset_p)
{
    const long row = blockIdx.x;            // (b*H+h)*S + s
    const int  s   = (int)(row % SS);
    const int  off = *offset_p;
    int valid = s + off + 1;
    if (valid > TT) valid = TT;
    int limit = ((s & ~127) + 128 + off + 127) & ~127;
    if (limit > TT) limit = TT;
    const __half* p = scores + row * (long)TT;
    __half* op = probs + row * (long)TT;
    const float scale = rsqrtf((float)(HD + RD));
    const int tid = threadIdx.x;
    const int e0 = tid * 8;

    float f[8];
    float m = -INFINITY;
    if (e0 < valid) {
        uint4 raw = *(const uint4*)(p + e0);
        const __half2* hp = (const __half2*)&raw;
        #pragma unroll
        for (int j = 0; j < 4; j++) {
            float2 v2 = __half22float2(hp[j]);
            f[j * 2]     = (e0 + j * 2 < valid)     ? v2.x * scale : -INFINITY;
            f[j * 2 + 1] = (e0 + j * 2 + 1 < valid) ? v2.y * scale : -INFINITY;
        }
        #pragma unroll
        for (int j = 0; j < 8; j++) m = fmaxf(m, f[j]);
    } else {
        #pragma unroll
        for (int j = 0; j < 8; j++) f[j] = -INFINITY;
    }

    __shared__ float red[32];
    for (int o = 16; o; o >>= 1) m = fmaxf(m, __shfl_xor_sync(0xffffffffu, m, o));
    if ((tid & 31) == 0) red[tid >> 5] = m;
    __syncthreads();
    if (tid < 32) {
        float t = (tid < 8) ? red[tid] : -INFINITY;
        for (int o = 16; o; o >>= 1) t = fmaxf(t, __shfl_xor_sync(0xffffffffu, t, o));
        if (tid == 0) red[0] = t;
    }
    __syncthreads();
    m = red[0];
    __syncthreads();

    float sum = 0.0f;
    #pragma unroll
    for (int j = 0; j < 8; j++) {
        float e = (f[j] == -INFINITY) ? 0.0f : expf(f[j] - m);
        f[j] = e;
        sum += e;
    }
    for (int o = 16; o; o >>= 1) sum += __shfl_xor_sync(0xffffffffu, sum, o);
    if ((tid & 31) == 0) red[tid >> 5] = sum;
    __syncthreads();
    if (tid < 32) {
        float t = (tid < 8) ? red[tid] : 0.0f;
        for (int o = 16; o; o >>= 1) t += __shfl_xor_sync(0xffffffffu, t, o);
        if (tid == 0) red[0] = t;
    }
    __syncthreads();
    float inv = 1.0f / red[0];

    if (e0 < limit) {
        uint4 outv;
        __half2* ho = (__half2*)&outv;
        #pragma unroll
        for (int j = 0; j < 4; j++)
            ho[j] = __floats2half2_rn(f[j * 2] * inv, f[j * 2 + 1] * inv);
        *(uint4*)(op + e0) = outv;
    }
}

// half->half 32x32 transpose, batched over z
__global__ void transpose_h(const __half* __restrict__ in, __half* __restrict__ out,
                            int R, int Cc, long sIn, long sOut)
{
    __shared__ __half t[32][33];
    const __half* ip = in + blockIdx.z * sIn;
    __half* op = out + blockIdx.z * sOut;
    const int c0 = blockIdx.x * 32, r0 = blockIdx.y * 32;
    for (int i = threadIdx.y; i < 32; i += 8)
        t[i][threadIdx.x] = ip[(long)(r0 + i) * Cc + c0 + threadIdx.x];
    __syncthreads();
    for (int i = threadIdx.y; i < 32; i += 8)
        op[(long)(c0 + i) * R + r0 + threadIdx.x] = t[threadIdx.x][i];
}

// float->half 32x32 transpose, batched over z (for W_UK)
__global__ void transpose_f2h(const float* __restrict__ in, __half* __restrict__ out,
                              int R, int Cc, long sIn, long sOut)
{
    __shared__ __half t[32][33];
    const float* ip = in + blockIdx.z * sIn;
    __half* op = out + blockIdx.z * sOut;
    const int c0 = blockIdx.x * 32, r0 = blockIdx.y * 32;
    for (int i = threadIdx.y; i < 32; i += 8)
        t[i][threadIdx.x] = __float2half_rn(ip[(long)(r0 + i) * Cc + c0 + threadIdx.x]);
    __syncthreads();
    for (int i = threadIdx.y; i < 32; i += 8)
        op[(long)(c0 + i) * R + r0 + threadIdx.x] = t[threadIdx.x][i];
}

// ================= host side ====================================================
template<typename T>
static T* sym_addr(const void* sym)
{
    void* p = nullptr;
    cudaGetSymbolAddress(&p, sym);
    return (T*)p;
}

extern "C" void kernel_launch(void* const* d_in, const int* in_sizes, int n_in,
                              void* d_out, int out_size)
{
    const float* x       = (const float*)d_in[0];
    const float* W_DKV   = (const float*)d_in[1];
    const float* W_KRope = (const float*)d_in[2];
    const float* W_Q     = (const float*)d_in[3];
    const float* W_UK    = (const float*)d_in[4];
    const float* W_UV    = (const float*)d_in[5];
    const float* W_O     = (const float*)d_in[6];
    const float* kvw     = (const float*)d_in[7];
    const int*   offset  = (const int*)d_in[8];
    float* out = (float*)d_out;

    static int s_init = 0;
    if (!s_init) {
        cudaFuncSetAttribute((const void*)gemm_h<0>, cudaFuncAttributeMaxDynamicSharedMemorySize, GEMM_SMEM);
        cudaFuncSetAttribute((const void*)gemm_h<1>, cudaFuncAttributeMaxDynamicSharedMemorySize, GEMM_SMEM);
        cudaFuncSetAttribute((const void*)gemm_proj3, cudaFuncAttributeMaxDynamicSharedMemorySize, GEMM_SMEM);
        cudaFuncSetAttribute((const void*)gemm_scores, cudaFuncAttributeMaxDynamicSharedMemorySize, GEMM_SMEM);
        cudaFuncSetAttribute((const void*)gemm_ctx3, cudaFuncAttributeMaxDynamicSharedMemorySize, GEMM_SMEM);
        s_init = 1;
    }

    __half* x16    = sym_addr<__half>(g_x16);
    __half* wdkv16 = sym_addr<__half>(g_wdkv16);
    __half* wkr16  = sym_addr<__half>(g_wkr16);
    __half* wq16   = sym_addr<__half>(g_wq16);
    __half* wo16   = sym_addr<__half>(g_wo16);
    __half* ckv16  = sym_addr<__half>(g_ckv16);
    __half* ckvT16 = sym_addr<__half>(g_ckvT16);
    __half* krope16= sym_addr<__half>(g_krope16);
    __half* q16    = sym_addr<__half>(g_q16);
    __half* qabs16 = sym_addr<__half>(g_qabs16);
    __half* wukT16 = sym_addr<__half>(g_wukT16);
    __half* scores16 = sym_addr<__half>(g_scores16);
    __half* probs16  = sym_addr<__half>(g_probs16);
    float*  ctxlat = sym_addr<float>(g_ctxlat);
    __half* ctx16  = sym_addr<__half>(g_ctx16);

    // 0) half-round inputs
    halfify_kernel<<<(ROWS*DIN/4 + 255)/256, 256>>>(x, x16, ROWS*DIN/4);
    halfify_kernel<<<(LL*DIN/4 + 255)/256, 256>>>(W_DKV, wdkv16, LL*DIN/4);
    halfify_kernel<<<(HH*RD*DIN/4 + 255)/256, 256>>>(W_KRope, wkr16, HH*RD*DIN/4);
    halfify_kernel<<<(QW*DIN/4 + 255)/256, 256>>>(W_Q, wq16, QW*DIN/4);
    halfify_kernel<<<(DIN*DOUT/4 + 255)/256, 256>>>(W_O, wo16, DIN*DOUT/4);

    // 1-3) fused projections
    {
        dim3 grid(36, 32, 1);
        gemm_proj3<<<grid, 256, GEMM_SMEM>>>(x16, wdkv16, wkr16, wq16,
                                             ckv16, krope16, q16);
    }
    rmsnorm_kernel<<<ROWS, 128>>>(ckv16, kvw);
    {
        dim3 grid(LL / 32, SS / 32, BB), block(32, 8);
        transpose_h<<<grid, block>>>(ckv16, ckvT16, SS, LL,
                                     (long)SS * LL, (long)LL * SS);
    }
    {
        long total = (long)ROWS * HH * HALF_RD;
        rope_kernel<<<(int)((total + 255) / 256), 256>>>(krope16, HH * RD, 0, offset);
        rope_kernel<<<(int)((total + 255) / 256), 256>>>(q16, QW, DOUT, offset);
    }

    // W_UK^T per head (fp32 -> half)
    {
        dim3 grid(LL / 32, HD / 32, HH), block(32, 8);
        transpose_f2h<<<grid, block>>>(W_UK, wukT16, HD, LL,
                                       (long)HD * LL, (long)LL * HD);
    }

    // 4) q_abs (half out)
    {
        dim3 grid(LL / 128, ROWS / 128, HH);
        gemm_h<1><<<grid, 256, GEMM_SMEM>>>(q16, wukT16, qabs16,
            HD, QW, HD, HH * LL,
            HH, 0, HD, 0, (long)LL * HD, 0, LL, nullptr, 0);
    }

    // 5) fused scores (causal block skip), half out
    {
        dim3 grid(TT / 128, SS / 128, BB * HH);
        gemm_scores<<<grid, 256, GEMM_SMEM>>>(q16, krope16, qabs16, ckv16,
                                              scores16, offset);
    }

    // 6) softmax: half scores -> half probs
    softmax_kernel<<<BB * HH * SS, 256>>>(scores16, probs16, offset);

    // 7) ctx_lat = probs @ ckvT (K clipped causally), fp32 out
    {
        dim3 grid(LL / 128, SS / 128, BB * HH);
        gemm_h<0><<<grid, 256, GEMM_SMEM>>>(probs16, ckvT16, ctxlat,
            TT, TT, SS, HH * LL,
            HH, (long)HH * SS * TT, (long)SS * TT,
            (long)LL * SS, 0,
            (long)SS * HH * LL, LL, offset, 1);
    }

    // 8) ctx = ctxlat @ W_UV^T per head (tf32x3, half out)
    {
        dim3 grid(1, ROWS / 128, HH);
        gemm_ctx3<<<grid, 256, GEMM_SMEM>>>(ctxlat, W_UV, ctx16);
    }

    // 9) out = ctx @ W_O^T (fp32 out)
    {
        dim3 grid(DIN / 128, ROWS / 128, 1);
        gemm_h<0><<<grid, 256, GEMM_SMEM>>>(ctx16, wo16, out,
            DOUT, DOUT, DOUT, DIN,
            1, 0, 0, 0, 0, 0, 0, nullptr, 0);
    }
}

// round 11
// speedup vs baseline: 1.3004x; 1.1396x over previous
#include <cuda_runtime.h>
#include <cuda_fp16.h>
#include <math.h>
#include <stdint.h>

// Problem constants
#define BB 2
#define SS 2048
#define TT 2048
#define DIN 2048
#define DOUT 2048
#define HH 16
#define RD 64
#define HALF_RD 32
#define LL 512
#define HD 128
#define ROWS (BB*SS)          // 4096
#define QW (DOUT+HH*RD)       // 3072

// ---------------- device scratch (static; no allocations) ---------------------
__device__ __align__(128) __half g_x16  [ROWS*DIN];
__device__ __align__(128) __half g_wdkv16[LL*DIN];
__device__ __align__(128) __half g_wkr16 [HH*RD*DIN];
__device__ __align__(128) __half g_wq16  [QW*DIN];
__device__ __align__(128) __half g_wo16  [DIN*DOUT];
__device__ __align__(128) __half g_wuv16 [DOUT*LL];
__device__ __align__(128) __half g_ckv16 [BB*SS*LL];
__device__ __align__(128) __half g_ckvT16[BB*LL*SS];
__device__ __align__(128) __half g_krope16[BB*SS*HH*RD];
__device__ __align__(128) __half g_q16   [BB*SS*QW];
__device__ __align__(128) __half g_qabs16[ROWS*HH*LL];
__device__ __align__(128) __half g_wukT16[LL*DOUT];
__device__ __align__(128) __half g_scores16[(long)BB*HH*SS*TT];
__device__ __align__(128) __half g_probs16 [(long)BB*HH*SS*TT];
__device__ __align__(128) __half g_ctxlat16[ROWS*HH*LL];
__device__ __align__(128) __half g_ctx16 [ROWS*DOUT];

// ================= helpers =====================================================
__device__ __forceinline__ uint32_t smem_u32(const void* p) {
    uint32_t a;
    asm("{ .reg .u64 t; cvta.to.shared.u64 t, %1; cvt.u32.u64 %0, t; }" : "=r"(a) : "l"(p));
    return a;
}
__device__ __forceinline__ void cp16(uint32_t dst, const void* src) {
    asm volatile("cp.async.cg.shared.global [%0], [%1], 16;" :: "r"(dst), "l"(src));
}
#define CP_COMMIT() asm volatile("cp.async.commit_group;" ::: "memory")
#define CP_WAIT2()  asm volatile("cp.async.wait_group 2;"  ::: "memory")
#define CP_WAIT0()  asm volatile("cp.async.wait_group 0;"  ::: "memory")

__device__ __forceinline__ void ldsm4(uint32_t* r, uint32_t addr) {
    asm volatile("ldmatrix.sync.aligned.m8n8.x4.shared.b16 {%0,%1,%2,%3}, [%4];"
                 : "=r"(r[0]), "=r"(r[1]), "=r"(r[2]), "=r"(r[3]) : "r"(addr));
}
__device__ __forceinline__ void mma_f16(float* c, const uint32_t* a, const uint32_t* b) {
    asm volatile(
        "mma.sync.aligned.m16n8k16.row.col.f32.f16.f16.f32 "
        "{%0,%1,%2,%3}, {%4,%5,%6,%7}, {%8,%9}, {%0,%1,%2,%3};"
        : "+f"(c[0]), "+f"(c[1]), "+f"(c[2]), "+f"(c[3])
        : "r"(a[0]), "r"(a[1]), "r"(a[2]), "r"(a[3]), "r"(b[0]), "r"(b[1]));
}

#define GEMM_SMEM 81920

// ================= FP16 GEMM tile engine: 128x128, K-chunk 32 ==================
// acc += A[0..128,:K] @ B[0..128,:K]^T ; half operands, fp32 accum.
// pitch 40 halves (80B) per row; stage = A(5120h)+B(5120h) = 20480 B. 4 stages.
__device__ __forceinline__ void gemm_tiles_h(
    const __half* __restrict__ A, const __half* __restrict__ B,
    int K, int lda, int ldb, float (*acc)[4][4], char* sm)
{
    const int tid  = threadIdx.x;
    const int lane = tid & 31;
    const int wid  = tid >> 5;
    const int wm   = wid >> 2;
    const int wn   = wid & 3;

    const uint32_t sbase = smem_u32(sm);

    const int aRow = wm * 64 + (lane & 7) + ((lane >> 3) & 1) * 8;
    const uint32_t aOff = (uint32_t)(aRow * 40 + ((lane >> 4) & 1) * 8) * 2;
    const int bRow = wn * 32 + (lane & 7) + ((lane >> 4) & 1) * 8;
    const uint32_t bOff = (uint32_t)(bRow * 40 + ((lane >> 3) & 1) * 8) * 2;

    const int crow = tid >> 2;          // 0..63
    const int cc   = (tid & 3) * 8;     // half offset 0,8,16,24
    auto issue = [&](int c) {
        const int k0 = c << 5;
        const uint32_t st = sbase + (uint32_t)(c & 3) * 20480;
        #pragma unroll
        for (int i = 0; i < 2; i++) {
            int row = crow + i * 64;
            uint32_t d = st + (uint32_t)(row * 40 + cc) * 2;
            cp16(d,             A + (long)row * lda + k0 + cc);
            cp16(d + 10240,     B + (long)row * ldb + k0 + cc);
        }
    };

    auto compute = [&](int c) {
        const uint32_t As = sbase + (uint32_t)(c & 3) * 20480;
        const uint32_t Bs = As + 10240;
        #pragma unroll
        for (int ks = 0; ks < 2; ks++) {
            uint32_t ah[4][4], bh[4][2];
            #pragma unroll
            for (int mt = 0; mt < 4; mt++)
                ldsm4(ah[mt], As + aOff + (uint32_t)(mt * 16 * 40 + ks * 16) * 2);
            #pragma unroll
            for (int np = 0; np < 2; np++) {
                uint32_t raw[4];
                ldsm4(raw, Bs + bOff + (uint32_t)(np * 16 * 40 + ks * 16) * 2);
                bh[np * 2][0] = raw[0]; bh[np * 2][1] = raw[1];
                bh[np * 2 + 1][0] = raw[2]; bh[np * 2 + 1][1] = raw[3];
            }
            #pragma unroll
            for (int mt = 0; mt < 4; mt++)
                #pragma unroll
                for (int nt = 0; nt < 4; nt++)
                    mma_f16(acc[mt][nt], ah[mt], bh[nt]);
        }
    };

    const int NC = K >> 5;
    if (0 < NC) issue(0); CP_COMMIT();
    if (1 < NC) issue(1); CP_COMMIT();
    if (2 < NC) issue(2); CP_COMMIT();
    for (int c = 0; c < NC; c++) {
        CP_WAIT2();
        __syncthreads();
        if (c + 3 < NC) issue(c + 3);
        CP_COMMIT();
        compute(c);
    }
    CP_WAIT0();
    __syncthreads();
}

// epilogue: OUTH=1 writes __half, else float
template<int OUTH>
__device__ __forceinline__ void gemm_epi(
    void* __restrict__ Cv, int ldc, int m0, int n0, float (*acc)[4][4])
{
    const int lane = threadIdx.x & 31;
    const int wid  = threadIdx.x >> 5;
    const int gid  = lane >> 2;
    const int tig  = lane & 3;
    const int wm   = wid >> 2;
    const int wn   = wid & 3;
    #pragma unroll
    for (int mt = 0; mt < 4; mt++) {
        #pragma unroll
        for (int nt = 0; nt < 4; nt++) {
            int r  = m0 + wm * 64 + mt * 16 + gid;
            int cc = n0 + wn * 32 + nt * 8 + tig * 2;
            if (OUTH) {
                __half* C = (__half*)Cv;
                *(__half2*)&C[(long)r * ldc + cc] =
                    __floats2half2_rn(acc[mt][nt][0], acc[mt][nt][1]);
                *(__half2*)&C[(long)(r + 8) * ldc + cc] =
                    __floats2half2_rn(acc[mt][nt][2], acc[mt][nt][3]);
            } else {
                float* C = (float*)Cv;
                float2 v0 = { acc[mt][nt][0], acc[mt][nt][1] };
                float2 v1 = { acc[mt][nt][2], acc[mt][nt][3] };
                *(float2*)&C[(long)r * ldc + cc]       = v0;
                *(float2*)&C[(long)(r + 8) * ldc + cc] = v1;
            }
        }
    }
}

#define ACC_INIT(acc) { _Pragma("unroll") for (int _m = 0; _m < 4; _m++) \
    _Pragma("unroll") for (int _n = 0; _n < 4; _n++) \
    _Pragma("unroll") for (int _i = 0; _i < 4; _i++) acc[_m][_n][_i] = 0.0f; }

// generic batched fp16 GEMM; kclip limits K causally (128-grain)
template<int OUTH>
__global__ void __launch_bounds__(256, 2)
gemm_h(const __half* __restrict__ Ab, const __half* __restrict__ Bb, void* __restrict__ Cb,
       int K, int lda, int ldb, int ldc,
       int zInner, long sAo, long sAi, long sBo, long sBi, long sCo, long sCi,
       const int* offset_p, int kclip)
{
    extern __shared__ char smc[];
    const int z  = blockIdx.z;
    const int zo = z / zInner, zi = z % zInner;
    const int m0 = blockIdx.y * 128;
    const int n0 = blockIdx.x * 128;
    if (kclip) {
        int lim = m0 + 128 + *offset_p;
        lim = (lim + 127) & ~127;
        if (lim < K) K = lim;
    }
    float acc[4][4][4];
    ACC_INIT(acc);
    gemm_tiles_h(Ab + zo * sAo + zi * sAi + (long)m0 * lda,
                 Bb + zo * sBo + zi * sBi + (long)n0 * ldb,
                 K, lda, ldb, acc, smc);
    if (OUTH)
        gemm_epi<1>((__half*)Cb + zo * sCo + zi * sCi, ldc, m0, n0, acc);
    else
        gemm_epi<0>((float*)Cb + zo * sCo + zi * sCi, ldc, m0, n0, acc);
}

// fused triple projection (half out): ckv 4 | krope 8 | q 24 blocks of 128
__global__ void __launch_bounds__(256, 2)
gemm_proj3(const __half* __restrict__ x,
           const __half* __restrict__ Wdkv, const __half* __restrict__ Wkr,
           const __half* __restrict__ Wq,
           __half* __restrict__ ckv, __half* __restrict__ krope, __half* __restrict__ q)
{
    extern __shared__ char smc[];
    const int bx = blockIdx.x;
    const __half* B; __half* C; int ldc, n0;
    if (bx < 4)       { B = Wdkv; C = ckv;   ldc = LL;       n0 = bx * 128; }
    else if (bx < 12) { B = Wkr;  C = krope; ldc = HH * RD;  n0 = (bx - 4) * 128; }
    else              { B = Wq;   C = q;     ldc = QW;       n0 = (bx - 12) * 128; }
    const int m0 = blockIdx.y * 128;
    float acc[4][4][4];
    ACC_INIT(acc);
    gemm_tiles_h(x + (long)m0 * DIN, B + (long)n0 * DIN, DIN, DIN, DIN, acc, smc);
    gemm_epi<1>(C, ldc, m0, n0, acc);
}

// fused scores: rope (K=64) + latent (K=512), causal block skip, half out
__global__ void __launch_bounds__(256, 2)
gemm_scores(const __half* __restrict__ q, const __half* __restrict__ krope,
            const __half* __restrict__ qabs, const __half* __restrict__ ckv,
            __half* __restrict__ scores, const int* __restrict__ offset_p)
{
    extern __shared__ char smc[];
    const int m0 = blockIdx.y * 128;
    const int n0 = blockIdx.x * 128;
    if (n0 > m0 + 127 + *offset_p) return;
    const int b = blockIdx.z >> 4;
    const int h = blockIdx.z & 15;

    float acc[4][4][4];
    ACC_INIT(acc);

    const __half* A1 = q + (long)b * SS * QW + DOUT + h * RD + (long)m0 * QW;
    const __half* B1 = krope + (long)b * SS * (HH * RD) + h * RD + (long)n0 * (HH * RD);
    gemm_tiles_h(A1, B1, RD, QW, HH * RD, acc, smc);

    const __half* A2 = qabs + (long)b * SS * (HH * LL) + h * LL + (long)m0 * (HH * LL);
    const __half* B2 = ckv + (long)b * SS * LL + (long)n0 * LL;
    gemm_tiles_h(A2, B2, LL, HH * LL, LL, acc, smc);

    gemm_epi<1>(scores + (long)blockIdx.z * SS * TT, TT, m0, n0, acc);
}

// ================= small kernels ===============================================
// one kernel, six fp32->fp16 segments (float4 granularity)
__global__ void halfify_all(
    const float* s0, __half* d0, int n0,
    const float* s1, __half* d1, int n1,
    const float* s2, __half* d2, int n2,
    const float* s3, __half* d3, int n3,
    const float* s4, __half* d4, int n4,
    const float* s5, __half* d5, int n5)
{
    long i = (long)blockIdx.x * blockDim.x + threadIdx.x;
    const float* s; __half* d;
    if (i < n0)              { s = s0; d = d0; }
    else if ((i -= n0) < n1) { s = s1; d = d1; }
    else if ((i -= n1) < n2) { s = s2; d = d2; }
    else if ((i -= n2) < n3) { s = s3; d = d3; }
    else if ((i -= n3) < n4) { s = s4; d = d4; }
    else if ((i -= n4) < n5) { s = s5; d = d5; }
    else return;
    float4 v = ((const float4*)s)[i];
    __half2* o = (__half2*)d;
    o[i * 2]     = __floats2half2_rn(v.x, v.y);
    o[i * 2 + 1] = __floats2half2_rn(v.z, v.w);
}

__global__ void rmsnorm_kernel(__half* __restrict__ data, const float* __restrict__ w)
{
    const int row = blockIdx.x;
    __half* p = data + (long)row * LL;
    float ss = 0.0f;
    float vals[4];
    #pragma unroll
    for (int i = 0; i < 4; i++) {
        vals[i] = __half2float(p[threadIdx.x + i * 128]);
        ss += vals[i] * vals[i];
    }
    __shared__ float red[32];
    for (int o = 16; o; o >>= 1) ss += __shfl_xor_sync(0xffffffffu, ss, o);
    if ((threadIdx.x & 31) == 0) red[threadIdx.x >> 5] = ss;
    __syncthreads();
    if (threadIdx.x < 32) {
        float v = (threadIdx.x < 4) ? red[threadIdx.x] : 0.0f;
        for (int o = 16; o; o >>= 1) v += __shfl_xor_sync(0xffffffffu, v, o);
        if (threadIdx.x == 0) red[0] = v;
    }
    __syncthreads();
    float rstd = rsqrtf(red[0] / (float)LL + 1e-6f);
    #pragma unroll
    for (int i = 0; i < 4; i++)
        p[threadIdx.x + i * 128] = __float2half_rn(vals[i] * rstd * w[threadIdx.x + i * 128]);
}

__global__ void rope_kernel(__half* __restrict__ data, int ld, int colbase,
                            const int* __restrict__ offset_p)
{
    long idx = (long)blockIdx.x * blockDim.x + threadIdx.x;
    const long total = (long)ROWS * HH * HALF_RD;
    if (idx >= total) return;
    int  j   = (int)(idx % HALF_RD);
    int  h   = (int)((idx / HALF_RD) % HH);
    long row = idx / (HALF_RD * HH);
    int  s   = (int)(row % SS);
    float pos = (float)(s + *offset_p);
    float inv = expf(-(float)j * (logf(10000.0f) / 32.0f));
    float ang = pos * inv;
    float c  = cosf(ang);
    float si = sinf(ang);
    __half* p = data + row * (long)ld + colbase + h * RD;
    float x1 = __half2float(p[j]), x2 = __half2float(p[j + HALF_RD]);
    p[j]           = __float2half_rn(x1 * c - x2 * si);
    p[j + HALF_RD] = __float2half_rn(x2 * c + x1 * si);
}

// masked scaled softmax; half scores in, half probs out; zero-fill to 128-grain
__global__ void __launch_bounds__(256)
softmax_kernel(const __half* __restrict__ scores, __half* __restrict__ probs,
               const int* __restrict__ offset_p)
{
    const long row = blockIdx.x;            // (b*H+h)*S + s
    const int  s   = (int)(row % SS);
    const int  off = *offset_p;
    int valid = s + off + 1;
    if (valid > TT) valid = TT;
    int limit = ((s & ~127) + 128 + off + 127) & ~127;
    if (limit > TT) limit = TT;
    const __half* p = scores + row * (long)TT;
    __half* op = probs + row * (long)TT;
    const float scale = rsqrtf((float)(HD + RD));
    const int tid = threadIdx.x;
    const int e0 = tid * 8;

    float f[8];
    float m = -INFINITY;
    if (e0 < valid) {
        uint4 raw = *(const uint4*)(p + e0);
        const __half2* hp = (const __half2*)&raw;
        #pragma unroll
        for (int j = 0; j < 4; j++) {
            float2 v2 = __half22float2(hp[j]);
            f[j * 2]     = (e0 + j * 2 < valid)     ? v2.x * scale : -INFINITY;
            f[j * 2 + 1] = (e0 + j * 2 + 1 < valid) ? v2.y * scale : -INFINITY;
        }
        #pragma unroll
        for (int j = 0; j < 8; j++) m = fmaxf(m, f[j]);
    } else {
        #pragma unroll
        for (int j = 0; j < 8; j++) f[j] = -INFINITY;
    }

    __shared__ float red[32];
    for (int o = 16; o; o >>= 1) m = fmaxf(m, __shfl_xor_sync(0xffffffffu, m, o));
    if ((tid & 31) == 0) red[tid >> 5] = m;
    __syncthreads();
    if (tid < 32) {
        float t = (tid < 8) ? red[tid] : -INFINITY;
        for (int o = 16; o; o >>= 1) t = fmaxf(t, __shfl_xor_sync(0xffffffffu, t, o));
        if (tid == 0) red[0] = t;
    }
    __syncthreads();
    m = red[0];
    __syncthreads();

    float sum = 0.0f;
    #pragma unroll
    for (int j = 0; j < 8; j++) {
        float e = (f[j] == -INFINITY) ? 0.0f : expf(f[j] - m);
        f[j] = e;
        sum += e;
    }
    for (int o = 16; o; o >>= 1) sum += __shfl_xor_sync(0xffffffffu, sum, o);
    if ((tid & 31) == 0) red[tid >> 5] = sum;
    __syncthreads();
    if (tid < 32) {
        float t = (tid < 8) ? red[tid] : 0.0f;
        for (int o = 16; o; o >>= 1) t += __shfl_xor_sync(0xffffffffu, t, o);
        if (tid == 0) red[0] = t;
    }
    __syncthreads();
    float inv = 1.0f / red[0];

    if (e0 < limit) {
        uint4 outv;
        __half2* ho = (__half2*)&outv;
        #pragma unroll
        for (int j = 0; j < 4; j++)
            ho[j] = __floats2half2_rn(f[j * 2] * inv, f[j * 2 + 1] * inv);
        *(uint4*)(op + e0) = outv;
    }
}

// half->half 32x32 transpose, batched over z
__global__ void transpose_h(const __half* __restrict__ in, __half* __restrict__ out,
                            int R, int Cc, long sIn, long sOut)
{
    __shared__ __half t[32][33];
    const __half* ip = in + blockIdx.z * sIn;
    __half* op = out + blockIdx.z * sOut;
    const int c0 = blockIdx.x * 32, r0 = blockIdx.y * 32;
    for (int i = threadIdx.y; i < 32; i += 8)
        t[i][threadIdx.x] = ip[(long)(r0 + i) * Cc + c0 + threadIdx.x];
    __syncthreads();
    for (int i = threadIdx.y; i < 32; i += 8)
        op[(long)(c0 + i) * R + r0 + threadIdx.x] = t[threadIdx.x][i];
}

// float->half 32x32 transpose, batched over z (for W_UK)
__global__ void transpose_f2h(const float* __restrict__ in, __half* __restrict__ out,
                              int R, int Cc, long sIn, long sOut)
{
    __shared__ __half t[32][33];
    const float* ip = in + blockIdx.z * sIn;
    __half* op = out + blockIdx.z * sOut;
    const int c0 = blockIdx.x * 32, r0 = blockIdx.y * 32;
    for (int i = threadIdx.y; i < 32; i += 8)
        t[i][threadIdx.x] = __float2half_rn(ip[(long)(r0 + i) * Cc + c0 + threadIdx.x]);
    __syncthreads();
    for (int i = threadIdx.y; i < 32; i += 8)
        op[(long)(c0 + i) * R + r0 + threadIdx.x] = t[threadIdx.x][i];
}

// ================= host side ====================================================
template<typename T>
static T* sym_addr(const void* sym)
{
    void* p = nullptr;
    cudaGetSymbolAddress(&p, sym);
    return (T*)p;
}

extern "C" void kernel_launch(void* const* d_in, const int* in_sizes, int n_in,
                              void* d_out, int out_size)
{
    const float* x       = (const float*)d_in[0];
    const float* W_DKV   = (const float*)d_in[1];
    const float* W_KRope = (const float*)d_in[2];
    const float* W_Q     = (const float*)d_in[3];
    const float* W_UK    = (const float*)d_in[4];
    const float* W_UV    = (const float*)d_in[5];
    const float* W_O     = (const float*)d_in[6];
    const float* kvw     = (const float*)d_in[7];
    const int*   offset  = (const int*)d_in[8];
    float* out = (float*)d_out;

    static int s_init = 0;
    if (!s_init) {
        cudaFuncSetAttribute((const void*)gemm_h<0>, cudaFuncAttributeMaxDynamicSharedMemorySize, GEMM_SMEM);
        cudaFuncSetAttribute((const void*)gemm_h<1>, cudaFuncAttributeMaxDynamicSharedMemorySize, GEMM_SMEM);
        cudaFuncSetAttribute((const void*)gemm_proj3, cudaFuncAttributeMaxDynamicSharedMemorySize, GEMM_SMEM);
        cudaFuncSetAttribute((const void*)gemm_scores, cudaFuncAttributeMaxDynamicSharedMemorySize, GEMM_SMEM);
        s_init = 1;
    }

    __half* x16    = sym_addr<__half>(g_x16);
    __half* wdkv16 = sym_addr<__half>(g_wdkv16);
    __half* wkr16  = sym_addr<__half>(g_wkr16);
    __half* wq16   = sym_addr<__half>(g_wq16);
    __half* wo16   = sym_addr<__half>(g_wo16);
    __half* wuv16  = sym_addr<__half>(g_wuv16);
    __half* ckv16  = sym_addr<__half>(g_ckv16);
    __half* ckvT16 = sym_addr<__half>(g_ckvT16);
    __half* krope16= sym_addr<__half>(g_krope16);
    __half* q16    = sym_addr<__half>(g_q16);
    __half* qabs16 = sym_addr<__half>(g_qabs16);
    __half* wukT16 = sym_addr<__half>(g_wukT16);
    __half* scores16 = sym_addr<__half>(g_scores16);
    __half* probs16  = sym_addr<__half>(g_probs16);
    __half* ctxlat16 = sym_addr<__half>(g_ctxlat16);
    __half* ctx16  = sym_addr<__half>(g_ctx16);

    // 0) half-round all six fp32 inputs in ONE launch
    {
        const int nx = ROWS*DIN/4, n1 = LL*DIN/4, n2 = HH*RD*DIN/4;
        const int n3 = QW*DIN/4, n4 = DIN*DOUT/4, n5 = DOUT*LL/4;
        long total = (long)nx + n1 + n2 + n3 + n4 + n5;
        halfify_all<<<(int)((total + 255) / 256), 256>>>(
            x, x16, nx, W_DKV, wdkv16, n1, W_KRope, wkr16, n2,
            W_Q, wq16, n3, W_O, wo16, n4, W_UV, wuv16, n5);
    }

    // 1-3) fused projections
    {
        dim3 grid(36, 32, 1);
        gemm_proj3<<<grid, 256, GEMM_SMEM>>>(x16, wdkv16, wkr16, wq16,
                                             ckv16, krope16, q16);
    }
    rmsnorm_kernel<<<ROWS, 128>>>(ckv16, kvw);
    {
        dim3 grid(LL / 32, SS / 32, BB), block(32, 8);
        transpose_h<<<grid, block>>>(ckv16, ckvT16, SS, LL,
                                     (long)SS * LL, (long)LL * SS);
    }
    {
        long total = (long)ROWS * HH * HALF_RD;
        rope_kernel<<<(int)((total + 255) / 256), 256>>>(krope16, HH * RD, 0, offset);
        rope_kernel<<<(int)((total + 255) / 256), 256>>>(q16, QW, DOUT, offset);
    }

    // W_UK^T per head (fp32 -> half)
    {
        dim3 grid(LL / 32, HD / 32, HH), block(32, 8);
        transpose_f2h<<<grid, block>>>(W_UK, wukT16, HD, LL,
                                       (long)HD * LL, (long)LL * HD);
    }

    // 4) q_abs (half out)
    {
        dim3 grid(LL / 128, ROWS / 128, HH);
        gemm_h<1><<<grid, 256, GEMM_SMEM>>>(q16, wukT16, qabs16,
            HD, QW, HD, HH * LL,
            HH, 0, HD, 0, (long)LL * HD, 0, LL, nullptr, 0);
    }

    // 5) fused scores (causal block skip), half out
    {
        dim3 grid(TT / 128, SS / 128, BB * HH);
        gemm_scores<<<grid, 256, GEMM_SMEM>>>(q16, krope16, qabs16, ckv16,
                                              scores16, offset);
    }

    // 6) softmax: half scores -> half probs
    softmax_kernel<<<BB * HH * SS, 256>>>(scores16, probs16, offset);

    // 7) ctx_lat = probs @ ckvT (K clipped causally), half out
    {
        dim3 grid(LL / 128, SS / 128, BB * HH);
        gemm_h<1><<<grid, 256, GEMM_SMEM>>>(probs16, ckvT16, ctxlat16,
            TT, TT, SS, HH * LL,
            HH, (long)HH * SS * TT, (long)SS * TT,
            (long)LL * SS, 0,
            (long)SS * HH * LL, LL, offset, 1);
    }

    // 8) ctx = ctxlat @ W_UV^T per head (fp16, half out)
    {
        dim3 grid(HD / 128, ROWS / 128, HH);
        gemm_h<1><<<grid, 256, GEMM_SMEM>>>(ctxlat16, wuv16, ctx16,
            LL, HH * LL, LL, DOUT,
            HH, 0, LL, 0, (long)HD * LL, 0, HD, nullptr, 0);
    }

    // 9) out = ctx @ W_O^T (fp32 out)
    {
        dim3 grid(DIN / 128, ROWS / 128, 1);
        gemm_h<0><<<grid, 256, GEMM_SMEM>>>(ctx16, wo16, out,
            DOUT, DOUT, DOUT, DIN,
            1, 0, 0, 0, 0, 0, 0, nullptr, 0);
    }
}

// round 12
// speedup vs baseline: 1.3796x; 1.0609x over previous
#include <cuda_runtime.h>
#include <cuda_fp16.h>
#include <math.h>
#include <stdint.h>

// Problem constants
#define BB 2
#define SS 2048
#define TT 2048
#define DIN 2048
#define DOUT 2048
#define HH 16
#define RD 64
#define HALF_RD 32
#define LL 512
#define HD 128
#define ROWS (BB*SS)          // 4096
#define QW (DOUT+HH*RD)       // 3072

// ---------------- device scratch (static; no allocations) ---------------------
__device__ __align__(128) __half g_x16  [ROWS*DIN];
__device__ __align__(128) __half g_wdkv16[LL*DIN];
__device__ __align__(128) __half g_wkr16 [HH*RD*DIN];
__device__ __align__(128) __half g_wq16  [QW*DIN];
__device__ __align__(128) __half g_wo16  [DIN*DOUT];
__device__ __align__(128) __half g_wuv16 [DOUT*LL];
__device__ __align__(128) __half g_ckv16 [BB*SS*LL];
__device__ __align__(128) __half g_ckvT16[BB*LL*SS];
__device__ __align__(128) __half g_krope16[BB*SS*HH*RD];
__device__ __align__(128) __half g_q16   [BB*SS*QW];
__device__ __align__(128) __half g_qabs16[ROWS*HH*LL];
__device__ __align__(128) __half g_wukT16[LL*DOUT];
__device__ __align__(128) __half g_scores16[(long)BB*HH*SS*TT];
__device__ __align__(128) __half g_probs16 [(long)BB*HH*SS*TT];
__device__ __align__(128) __half g_ctxlat16[ROWS*HH*LL];
__device__ __align__(128) __half g_ctx16 [ROWS*DOUT];

// ================= helpers =====================================================
__device__ __forceinline__ uint32_t smem_u32(const void* p) {
    uint32_t a;
    asm("{ .reg .u64 t; cvta.to.shared.u64 t, %1; cvt.u32.u64 %0, t; }" : "=r"(a) : "l"(p));
    return a;
}
__device__ __forceinline__ void cp16(uint32_t dst, const void* src) {
    asm volatile("cp.async.cg.shared.global [%0], [%1], 16;" :: "r"(dst), "l"(src));
}
#define CP_COMMIT() asm volatile("cp.async.commit_group;" ::: "memory")
#define CP_WAIT1()  asm volatile("cp.async.wait_group 1;"  ::: "memory")
#define CP_WAIT0()  asm volatile("cp.async.wait_group 0;"  ::: "memory")

__device__ __forceinline__ void ldsm4(uint32_t* r, uint32_t addr) {
    asm volatile("ldmatrix.sync.aligned.m8n8.x4.shared.b16 {%0,%1,%2,%3}, [%4];"
                 : "=r"(r[0]), "=r"(r[1]), "=r"(r[2]), "=r"(r[3]) : "r"(addr));
}
__device__ __forceinline__ void mma_f16(float* c, const uint32_t* a, const uint32_t* b) {
    asm volatile(
        "mma.sync.aligned.m16n8k16.row.col.f32.f16.f16.f32 "
        "{%0,%1,%2,%3}, {%4,%5,%6,%7}, {%8,%9}, {%0,%1,%2,%3};"
        : "+f"(c[0]), "+f"(c[1]), "+f"(c[2]), "+f"(c[3])
        : "r"(a[0]), "r"(a[1]), "r"(a[2]), "r"(a[3]), "r"(b[0]), "r"(b[1]));
}

// ================= FP16 GEMM tile engine: 128x128, K-chunk 64, 3 stages =========
// acc += A[0..128,:K] @ B[0..128,:K]^T ; half operands, fp32 accum. K % 64 == 0.
// pitch 72 halves (144B, conflict-free); stage = A(18432B)+B(18432B) = 36864 B.
#define STGB 36864
#define GEMM_SMEM (3*STGB)      // 110592 B; x2 CTA = 216 KB <= 228 KB

__device__ __forceinline__ void gemm_tiles_h(
    const __half* __restrict__ A, const __half* __restrict__ B,
    int K, int lda, int ldb, float (*acc)[4][4], char* sm)
{
    const int tid  = threadIdx.x;
    const int lane = tid & 31;
    const int wid  = tid >> 5;
    const int wm   = wid >> 2;
    const int wn   = wid & 3;

    const uint32_t sbase = smem_u32(sm);

    const int aRow = wm * 64 + (lane & 7) + ((lane >> 3) & 1) * 8;
    const uint32_t aOff = (uint32_t)(aRow * 72 + ((lane >> 4) & 1) * 8) * 2;
    const int bRow = wn * 32 + (lane & 7) + ((lane >> 4) & 1) * 8;
    const uint32_t bOff = (uint32_t)(bRow * 72 + ((lane >> 3) & 1) * 8) * 2;

    // loader: 128 rows x 64 halves per operand; 1024 cp16 each; 8 cp16/thread
    auto issue = [&](int c) {
        const int k0 = c << 6;
        const uint32_t st = sbase + (uint32_t)(c % 3) * STGB;
        #pragma unroll
        for (int i = 0; i < 4; i++) {
            int op = tid + i * 256;          // 0..1023
            int row = op >> 3, c8 = (op & 7) * 8;
            uint32_t d = st + (uint32_t)(row * 72 + c8) * 2;
            cp16(d,           A + (long)row * lda + k0 + c8);
            cp16(d + 18432,   B + (long)row * ldb + k0 + c8);
        }
    };

    auto compute = [&](int c) {
        const uint32_t As = sbase + (uint32_t)(c % 3) * STGB;
        const uint32_t Bs = As + 18432;
        #pragma unroll
        for (int ks = 0; ks < 4; ks++) {
            uint32_t ah[4][4], bh[4][2];
            #pragma unroll
            for (int mt = 0; mt < 4; mt++)
                ldsm4(ah[mt], As + aOff + (uint32_t)(mt * 16 * 72 + ks * 16) * 2);
            #pragma unroll
            for (int np = 0; np < 2; np++) {
                uint32_t raw[4];
                ldsm4(raw, Bs + bOff + (uint32_t)(np * 16 * 72 + ks * 16) * 2);
                bh[np * 2][0] = raw[0]; bh[np * 2][1] = raw[1];
                bh[np * 2 + 1][0] = raw[2]; bh[np * 2 + 1][1] = raw[3];
            }
            #pragma unroll
            for (int mt = 0; mt < 4; mt++)
                #pragma unroll
                for (int nt = 0; nt < 4; nt++)
                    mma_f16(acc[mt][nt], ah[mt], bh[nt]);
        }
    };

    const int NC = K >> 6;                   // K/64 >= 1
    issue(0); CP_COMMIT();
    if (1 < NC) issue(1);
    CP_COMMIT();
    for (int c = 0; c < NC; c++) {
        CP_WAIT1();                          // groups retire in order -> chunk c done
        __syncthreads();
        if (c + 2 < NC) issue(c + 2);
        CP_COMMIT();
        compute(c);
    }
    CP_WAIT0();                              // drain before smem reuse (2nd call)
    __syncthreads();
}

// epilogue: OUTH=1 writes __half, else float
template<int OUTH>
__device__ __forceinline__ void gemm_epi(
    void* __restrict__ Cv, int ldc, int m0, int n0, float (*acc)[4][4])
{
    const int lane = threadIdx.x & 31;
    const int wid  = threadIdx.x >> 5;
    const int gid  = lane >> 2;
    const int tig  = lane & 3;
    const int wm   = wid >> 2;
    const int wn   = wid & 3;
    #pragma unroll
    for (int mt = 0; mt < 4; mt++) {
        #pragma unroll
        for (int nt = 0; nt < 4; nt++) {
            int r  = m0 + wm * 64 + mt * 16 + gid;
            int cc = n0 + wn * 32 + nt * 8 + tig * 2;
            if (OUTH) {
                __half* C = (__half*)Cv;
                *(__half2*)&C[(long)r * ldc + cc] =
                    __floats2half2_rn(acc[mt][nt][0], acc[mt][nt][1]);
                *(__half2*)&C[(long)(r + 8) * ldc + cc] =
                    __floats2half2_rn(acc[mt][nt][2], acc[mt][nt][3]);
            } else {
                float* C = (float*)Cv;
                float2 v0 = { acc[mt][nt][0], acc[mt][nt][1] };
                float2 v1 = { acc[mt][nt][2], acc[mt][nt][3] };
                *(float2*)&C[(long)r * ldc + cc]       = v0;
                *(float2*)&C[(long)(r + 8) * ldc + cc] = v1;
            }
        }
    }
}

#define ACC_INIT(acc) { _Pragma("unroll") for (int _m = 0; _m < 4; _m++) \
    _Pragma("unroll") for (int _n = 0; _n < 4; _n++) \
    _Pragma("unroll") for (int _i = 0; _i < 4; _i++) acc[_m][_n][_i] = 0.0f; }

// generic batched fp16 GEMM; kclip limits K causally (128-grain, mult of 64)
template<int OUTH>
__global__ void __launch_bounds__(256, 2)
gemm_h(const __half* __restrict__ Ab, const __half* __restrict__ Bb, void* __restrict__ Cb,
       int K, int lda, int ldb, int ldc,
       int zInner, long sAo, long sAi, long sBo, long sBi, long sCo, long sCi,
       const int* offset_p, int kclip)
{
    extern __shared__ char smc[];
    const int z  = blockIdx.z;
    const int zo = z / zInner, zi = z % zInner;
    const int m0 = blockIdx.y * 128;
    const int n0 = blockIdx.x * 128;
    if (kclip) {
        int lim = m0 + 128 + *offset_p;
        lim = (lim + 127) & ~127;
        if (lim < K) K = lim;
    }
    float acc[4][4][4];
    ACC_INIT(acc);
    gemm_tiles_h(Ab + zo * sAo + zi * sAi + (long)m0 * lda,
                 Bb + zo * sBo + zi * sBi + (long)n0 * ldb,
                 K, lda, ldb, acc, smc);
    if (OUTH)
        gemm_epi<1>((__half*)Cb + zo * sCo + zi * sCi, ldc, m0, n0, acc);
    else
        gemm_epi<0>((float*)Cb + zo * sCo + zi * sCi, ldc, m0, n0, acc);
}

// fused triple projection (half out): ckv 4 | krope 8 | q 24 blocks of 128
__global__ void __launch_bounds__(256, 2)
gemm_proj3(const __half* __restrict__ x,
           const __half* __restrict__ Wdkv, const __half* __restrict__ Wkr,
           const __half* __restrict__ Wq,
           __half* __restrict__ ckv, __half* __restrict__ krope, __half* __restrict__ q)
{
    extern __shared__ char smc[];
    const int bx = blockIdx.x;
    const __half* B; __half* C; int ldc, n0;
    if (bx < 4)       { B = Wdkv; C = ckv;   ldc = LL;       n0 = bx * 128; }
    else if (bx < 12) { B = Wkr;  C = krope; ldc = HH * RD;  n0 = (bx - 4) * 128; }
    else              { B = Wq;   C = q;     ldc = QW;       n0 = (bx - 12) * 128; }
    const int m0 = blockIdx.y * 128;
    float acc[4][4][4];
    ACC_INIT(acc);
    gemm_tiles_h(x + (long)m0 * DIN, B + (long)n0 * DIN, DIN, DIN, DIN, acc, smc);
    gemm_epi<1>(C, ldc, m0, n0, acc);
}

// fused scores: rope (K=64) + latent (K=512), causal block skip, half out
__global__ void __launch_bounds__(256, 2)
gemm_scores(const __half* __restrict__ q, const __half* __restrict__ krope,
            const __half* __restrict__ qabs, const __half* __restrict__ ckv,
            __half* __restrict__ scores, const int* __restrict__ offset_p)
{
    extern __shared__ char smc[];
    const int m0 = blockIdx.y * 128;
    const int n0 = blockIdx.x * 128;
    if (n0 > m0 + 127 + *offset_p) return;
    const int b = blockIdx.z >> 4;
    const int h = blockIdx.z & 15;

    float acc[4][4][4];
    ACC_INIT(acc);

    const __half* A1 = q + (long)b * SS * QW + DOUT + h * RD + (long)m0 * QW;
    const __half* B1 = krope + (long)b * SS * (HH * RD) + h * RD + (long)n0 * (HH * RD);
    gemm_tiles_h(A1, B1, RD, QW, HH * RD, acc, smc);

    const __half* A2 = qabs + (long)b * SS * (HH * LL) + h * LL + (long)m0 * (HH * LL);
    const __half* B2 = ckv + (long)b * SS * LL + (long)n0 * LL;
    gemm_tiles_h(A2, B2, LL, HH * LL, LL, acc, smc);

    gemm_epi<1>(scores + (long)blockIdx.z * SS * TT, TT, m0, n0, acc);
}

// ================= small kernels ===============================================
// one kernel, six fp32->fp16 segments (float4 granularity)
__global__ void halfify_all(
    const float* s0, __half* d0, int n0,
    const float* s1, __half* d1, int n1,
    const float* s2, __half* d2, int n2,
    const float* s3, __half* d3, int n3,
    const float* s4, __half* d4, int n4,
    const float* s5, __half* d5, int n5)
{
    long i = (long)blockIdx.x * blockDim.x + threadIdx.x;
    const float* s; __half* d;
    if (i < n0)              { s = s0; d = d0; }
    else if ((i -= n0) < n1) { s = s1; d = d1; }
    else if ((i -= n1) < n2) { s = s2; d = d2; }
    else if ((i -= n2) < n3) { s = s3; d = d3; }
    else if ((i -= n3) < n4) { s = s4; d = d4; }
    else if ((i -= n4) < n5) { s = s5; d = d5; }
    else return;
    float4 v = ((const float4*)s)[i];
    __half2* o = (__half2*)d;
    o[i * 2]     = __floats2half2_rn(v.x, v.y);
    o[i * 2 + 1] = __floats2half2_rn(v.z, v.w);
}

__global__ void rmsnorm_kernel(__half* __restrict__ data, const float* __restrict__ w)
{
    const int row = blockIdx.x;
    __half* p = data + (long)row * LL;
    float ss = 0.0f;
    float vals[4];
    #pragma unroll
    for (int i = 0; i < 4; i++) {
        vals[i] = __half2float(p[threadIdx.x + i * 128]);
        ss += vals[i] * vals[i];
    }
    __shared__ float red[32];
    for (int o = 16; o; o >>= 1) ss += __shfl_xor_sync(0xffffffffu, ss, o);
    if ((threadIdx.x & 31) == 0) red[threadIdx.x >> 5] = ss;
    __syncthreads();
    if (threadIdx.x < 32) {
        float v = (threadIdx.x < 4) ? red[threadIdx.x] : 0.0f;
        for (int o = 16; o; o >>= 1) v += __shfl_xor_sync(0xffffffffu, v, o);
        if (threadIdx.x == 0) red[0] = v;
    }
    __syncthreads();
    float rstd = rsqrtf(red[0] / (float)LL + 1e-6f);
    #pragma unroll
    for (int i = 0; i < 4; i++)
        p[threadIdx.x + i * 128] = __float2half_rn(vals[i] * rstd * w[threadIdx.x + i * 128]);
}

// both rope applications in one launch: seg 0 = krope (ld HH*RD, colbase 0),
// seg 1 = q (ld QW, colbase DOUT)
__global__ void rope_both(__half* __restrict__ krope, __half* __restrict__ q,
                          const int* __restrict__ offset_p)
{
    const long per = (long)ROWS * HH * HALF_RD;
    long idx = (long)blockIdx.x * blockDim.x + threadIdx.x;
    __half* data; int ld, colbase;
    if (idx < per) { data = krope; ld = HH * RD; colbase = 0; }
    else if ((idx -= per) < per) { data = q; ld = QW; colbase = DOUT; }
    else return;
    int  j   = (int)(idx % HALF_RD);
    int  h   = (int)((idx / HALF_RD) % HH);
    long row = idx / (HALF_RD * HH);
    int  s   = (int)(row % SS);
    float pos = (float)(s + *offset_p);
    float inv = expf(-(float)j * (logf(10000.0f) / 32.0f));
    float ang = pos * inv;
    float c  = cosf(ang);
    float si = sinf(ang);
    __half* p = data + row * (long)ld + colbase + h * RD;
    float x1 = __half2float(p[j]), x2 = __half2float(p[j + HALF_RD]);
    p[j]           = __float2half_rn(x1 * c - x2 * si);
    p[j + HALF_RD] = __float2half_rn(x2 * c + x1 * si);
}

// masked scaled softmax; half scores in, half probs out; zero-fill to 128-grain
__global__ void __launch_bounds__(256)
softmax_kernel(const __half* __restrict__ scores, __half* __restrict__ probs,
               const int* __restrict__ offset_p)
{
    const long row = blockIdx.x;            // (b*H+h)*S + s
    const int  s   = (int)(row % SS);
    const int  off = *offset_p;
    int valid = s + off + 1;
    if (valid > TT) valid = TT;
    int limit = ((s & ~127) + 128 + off + 127) & ~127;
    if (limit > TT) limit = TT;
    const __half* p = scores + row * (long)TT;
    __half* op = probs + row * (long)TT;
    const float scale = rsqrtf((float)(HD + RD));
    const int tid = threadIdx.x;
    const int e0 = tid * 8;

    float f[8];
    float m = -INFINITY;
    if (e0 < valid) {
        uint4 raw = *(const uint4*)(p + e0);
        const __half2* hp = (const __half2*)&raw;
        #pragma unroll
        for (int j = 0; j < 4; j++) {
            float2 v2 = __half22float2(hp[j]);
            f[j * 2]     = (e0 + j * 2 < valid)     ? v2.x * scale : -INFINITY;
            f[j * 2 + 1] = (e0 + j * 2 + 1 < valid) ? v2.y * scale : -INFINITY;
        }
        #pragma unroll
        for (int j = 0; j < 8; j++) m = fmaxf(m, f[j]);
    } else {
        #pragma unroll
        for (int j = 0; j < 8; j++) f[j] = -INFINITY;
    }

    __shared__ float red[32];
    for (int o = 16; o; o >>= 1) m = fmaxf(m, __shfl_xor_sync(0xffffffffu, m, o));
    if ((tid & 31) == 0) red[tid >> 5] = m;
    __syncthreads();
    if (tid < 32) {
        float t = (tid < 8) ? red[tid] : -INFINITY;
        for (int o = 16; o; o >>= 1) t = fmaxf(t, __shfl_xor_sync(0xffffffffu, t, o));
        if (tid == 0) red[0] = t;
    }
    __syncthreads();
    m = red[0];
    __syncthreads();

    float sum = 0.0f;
    #pragma unroll
    for (int j = 0; j < 8; j++) {
        float e = (f[j] == -INFINITY) ? 0.0f : expf(f[j] - m);
        f[j] = e;
        sum += e;
    }
    for (int o = 16; o; o >>= 1) sum += __shfl_xor_sync(0xffffffffu, sum, o);
    if ((tid & 31) == 0) red[tid >> 5] = sum;
    __syncthreads();
    if (tid < 32) {
        float t = (tid < 8) ? red[tid] : 0.0f;
        for (int o = 16; o; o >>= 1) t += __shfl_xor_sync(0xffffffffu, t, o);
        if (tid == 0) red[0] = t;
    }
    __syncthreads();
    float inv = 1.0f / red[0];

    if (e0 < limit) {
        uint4 outv;
        __half2* ho = (__half2*)&outv;
        #pragma unroll
        for (int j = 0; j < 4; j++)
            ho[j] = __floats2half2_rn(f[j * 2] * inv, f[j * 2 + 1] * inv);
        *(uint4*)(op + e0) = outv;
    }
}

// half->half 32x32 transpose, batched over z
__global__ void transpose_h(const __half* __restrict__ in, __half* __restrict__ out,
                            int R, int Cc, long sIn, long sOut)
{
    __shared__ __half t[32][33];
    const __half* ip = in + blockIdx.z * sIn;
    __half* op = out + blockIdx.z * sOut;
    const int c0 = blockIdx.x * 32, r0 = blockIdx.y * 32;
    for (int i = threadIdx.y; i < 32; i += 8)
        t[i][threadIdx.x] = ip[(long)(r0 + i) * Cc + c0 + threadIdx.x];
    __syncthreads();
    for (int i = threadIdx.y; i < 32; i += 8)
        op[(long)(c0 + i) * R + r0 + threadIdx.x] = t[threadIdx.x][i];
}

// float->half 32x32 transpose, batched over z (for W_UK)
__global__ void transpose_f2h(const float* __restrict__ in, __half* __restrict__ out,
                              int R, int Cc, long sIn, long sOut)
{
    __shared__ __half t[32][33];
    const float* ip = in + blockIdx.z * sIn;
    __half* op = out + blockIdx.z * sOut;
    const int c0 = blockIdx.x * 32, r0 = blockIdx.y * 32;
    for (int i = threadIdx.y; i < 32; i += 8)
        t[i][threadIdx.x] = __float2half_rn(ip[(long)(r0 + i) * Cc + c0 + threadIdx.x]);
    __syncthreads();
    for (int i = threadIdx.y; i < 32; i += 8)
        op[(long)(c0 + i) * R + r0 + threadIdx.x] = t[threadIdx.x][i];
}

// ================= host side ====================================================
template<typename T>
static T* sym_addr(const void* sym)
{
    void* p = nullptr;
    cudaGetSymbolAddress(&p, sym);
    return (T*)p;
}

extern "C" void kernel_launch(void* const* d_in, const int* in_sizes, int n_in,
                              void* d_out, int out_size)
{
    const float* x       = (const float*)d_in[0];
    const float* W_DKV   = (const float*)d_in[1];
    const float* W_KRope = (const float*)d_in[2];
    const float* W_Q     = (const float*)d_in[3];
    const float* W_UK    = (const float*)d_in[4];
    const float* W_UV    = (const float*)d_in[5];
    const float* W_O     = (const float*)d_in[6];
    const float* kvw     = (const float*)d_in[7];
    const int*   offset  = (const int*)d_in[8];
    float* out = (float*)d_out;

    static int s_init = 0;
    if (!s_init) {
        cudaFuncSetAttribute((const void*)gemm_h<0>, cudaFuncAttributeMaxDynamicSharedMemorySize, GEMM_SMEM);
        cudaFuncSetAttribute((const void*)gemm_h<1>, cudaFuncAttributeMaxDynamicSharedMemorySize, GEMM_SMEM);
        cudaFuncSetAttribute((const void*)gemm_proj3, cudaFuncAttributeMaxDynamicSharedMemorySize, GEMM_SMEM);
        cudaFuncSetAttribute((const void*)gemm_scores, cudaFuncAttributeMaxDynamicSharedMemorySize, GEMM_SMEM);
        s_init = 1;
    }

    __half* x16    = sym_addr<__half>(g_x16);
    __half* wdkv16 = sym_addr<__half>(g_wdkv16);
    __half* wkr16  = sym_addr<__half>(g_wkr16);
    __half* wq16   = sym_addr<__half>(g_wq16);
    __half* wo16   = sym_addr<__half>(g_wo16);
    __half* wuv16  = sym_addr<__half>(g_wuv16);
    __half* ckv16  = sym_addr<__half>(g_ckv16);
    __half* ckvT16 = sym_addr<__half>(g_ckvT16);
    __half* krope16= sym_addr<__half>(g_krope16);
    __half* q16    = sym_addr<__half>(g_q16);
    __half* qabs16 = sym_addr<__half>(g_qabs16);
    __half* wukT16 = sym_addr<__half>(g_wukT16);
    __half* scores16 = sym_addr<__half>(g_scores16);
    __half* probs16  = sym_addr<__half>(g_probs16);
    __half* ctxlat16 = sym_addr<__half>(g_ctxlat16);
    __half* ctx16  = sym_addr<__half>(g_ctx16);

    // 0) half-round all six fp32 inputs in ONE launch
    {
        const int nx = ROWS*DIN/4, n1 = LL*DIN/4, n2 = HH*RD*DIN/4;
        const int n3 = QW*DIN/4, n4 = DIN*DOUT/4, n5 = DOUT*LL/4;
        long total = (long)nx + n1 + n2 + n3 + n4 + n5;
        halfify_all<<<(int)((total + 255) / 256), 256>>>(
            x, x16, nx, W_DKV, wdkv16, n1, W_KRope, wkr16, n2,
            W_Q, wq16, n3, W_O, wo16, n4, W_UV, wuv16, n5);
    }

    // 1-3) fused projections
    {
        dim3 grid(36, 32, 1);
        gemm_proj3<<<grid, 256, GEMM_SMEM>>>(x16, wdkv16, wkr16, wq16,
                                             ckv16, krope16, q16);
    }
    rmsnorm_kernel<<<ROWS, 128>>>(ckv16, kvw);
    {
        dim3 grid(LL / 32, SS / 32, BB), block(32, 8);
        transpose_h<<<grid, block>>>(ckv16, ckvT16, SS, LL,
                                     (long)SS * LL, (long)LL * SS);
    }
    {
        long total = 2L * ROWS * HH * HALF_RD;
        rope_both<<<(int)((total + 255) / 256), 256>>>(krope16, q16, offset);
    }

    // W_UK^T per head (fp32 -> half)
    {
        dim3 grid(LL / 32, HD / 32, HH), block(32, 8);
        transpose_f2h<<<grid, block>>>(W_UK, wukT16, HD, LL,
                                       (long)HD * LL, (long)LL * HD);
    }

    // 4) q_abs (half out)
    {
        dim3 grid(LL / 128, ROWS / 128, HH);
        gemm_h<1><<<grid, 256, GEMM_SMEM>>>(q16, wukT16, qabs16,
            HD, QW, HD, HH * LL,
            HH, 0, HD, 0, (long)LL * HD, 0, LL, nullptr, 0);
    }

    // 5) fused scores (causal block skip), half out
    {
        dim3 grid(TT / 128, SS / 128, BB * HH);
        gemm_scores<<<grid, 256, GEMM_SMEM>>>(q16, krope16, qabs16, ckv16,
                                              scores16, offset);
    }

    // 6) softmax: half scores -> half probs
    softmax_kernel<<<BB * HH * SS, 256>>>(scores16, probs16, offset);

    // 7) ctx_lat = probs @ ckvT (K clipped causally), half out
    {
        dim3 grid(LL / 128, SS / 128, BB * HH);
        gemm_h<1><<<grid, 256, GEMM_SMEM>>>(probs16, ckvT16, ctxlat16,
            TT, TT, SS, HH * LL,
            HH, (long)HH * SS * TT, (long)SS * TT,
            (long)LL * SS, 0,
            (long)SS * HH * LL, LL, offset, 1);
    }

    // 8) ctx = ctxlat @ W_UV^T per head (fp16, half out)
    {
        dim3 grid(HD / 128, ROWS / 128, HH);
        gemm_h<1><<<grid, 256, GEMM_SMEM>>>(ctxlat16, wuv16, ctx16,
            LL, HH * LL, LL, DOUT,
            HH, 0, LL, 0, (long)HD * LL, 0, HD, nullptr, 0);
    }

    // 9) out = ctx @ W_O^T (fp32 out)
    {
        dim3 grid(DIN / 128, ROWS / 128, 1);
        gemm_h<0><<<grid, 256, GEMM_SMEM>>>(ctx16, wo16, out,
            DOUT, DOUT, DOUT, DIN,
            1, 0, 0, 0, 0, 0, 0, nullptr, 0);
    }
}

// round 13
// speedup vs baseline: 1.4209x; 1.0299x over previous
#include <cuda_runtime.h>
#include <cuda_fp16.h>
#include <math.h>
#include <stdint.h>

// Problem constants
#define BB 2
#define SS 2048
#define TT 2048
#define DIN 2048
#define DOUT 2048
#define HH 16
#define RD 64
#define HALF_RD 32
#define LL 512
#define HD 128
#define ROWS (BB*SS)          // 4096
#define QW (DOUT+HH*RD)       // 3072

// ---------------- device scratch (static; no allocations) ---------------------
__device__ __align__(128) __half g_x16  [ROWS*DIN];
__device__ __align__(128) __half g_wdkv16[LL*DIN];
__device__ __align__(128) __half g_wkr16 [HH*RD*DIN];
__device__ __align__(128) __half g_wq16  [QW*DIN];
__device__ __align__(128) __half g_wo16  [DIN*DOUT];
__device__ __align__(128) __half g_wuv16 [DOUT*LL];
__device__ __align__(128) __half g_ckv16 [BB*SS*LL];
__device__ __align__(128) __half g_ckvT16[BB*LL*SS];
__device__ __align__(128) __half g_krope16[BB*SS*HH*RD];
__device__ __align__(128) __half g_q16   [BB*SS*QW];
__device__ __align__(128) __half g_qabs16[ROWS*HH*LL];
__device__ __align__(128) __half g_wukT16[LL*DOUT];
__device__ __align__(128) __half g_scores16[(long)BB*HH*SS*TT];
__device__ __align__(128) __half g_probs16 [(long)BB*HH*SS*TT];
__device__ __align__(128) __half g_ctxlat16[ROWS*HH*LL];
__device__ __align__(128) __half g_ctx16 [ROWS*DOUT];

// ================= helpers =====================================================
__device__ __forceinline__ uint32_t smem_u32(const void* p) {
    uint32_t a;
    asm("{ .reg .u64 t; cvta.to.shared.u64 t, %1; cvt.u32.u64 %0, t; }" : "=r"(a) : "l"(p));
    return a;
}
__device__ __forceinline__ void cp16(uint32_t dst, const void* src) {
    asm volatile("cp.async.cg.shared.global [%0], [%1], 16;" :: "r"(dst), "l"(src));
}
#define CP_COMMIT() asm volatile("cp.async.commit_group;" ::: "memory")
#define CP_WAIT1()  asm volatile("cp.async.wait_group 1;"  ::: "memory")
#define CP_WAIT0()  asm volatile("cp.async.wait_group 0;"  ::: "memory")

__device__ __forceinline__ void ldsm4(uint32_t* r, uint32_t addr) {
    asm volatile("ldmatrix.sync.aligned.m8n8.x4.shared.b16 {%0,%1,%2,%3}, [%4];"
                 : "=r"(r[0]), "=r"(r[1]), "=r"(r[2]), "=r"(r[3]) : "r"(addr));
}
__device__ __forceinline__ void mma_f16(float* c, const uint32_t* a, const uint32_t* b) {
    asm volatile(
        "mma.sync.aligned.m16n8k16.row.col.f32.f16.f16.f32 "
        "{%0,%1,%2,%3}, {%4,%5,%6,%7}, {%8,%9}, {%0,%1,%2,%3};"
        : "+f"(c[0]), "+f"(c[1]), "+f"(c[2]), "+f"(c[3])
        : "r"(a[0]), "r"(a[1]), "r"(a[2]), "r"(a[3]), "r"(b[0]), "r"(b[1]));
}

// ================= FP16 GEMM tile engine: 128x128, K-chunk 64, 3 stages =========
// acc += A[0..128,:K] @ B[0..128,:K]^T ; half operands, fp32 accum. K % 64 == 0.
// pitch 72 halves (144B, conflict-free); stage = A(18432B)+B(18432B) = 36864 B.
#define STGB 36864
#define GEMM_SMEM (3*STGB)      // 110592 B; x2 CTA = 216 KB <= 228 KB

__device__ __forceinline__ void gemm_tiles_h(
    const __half* __restrict__ A, const __half* __restrict__ B,
    int K, int lda, int ldb, float (*acc)[4][4], char* sm)
{
    const int tid  = threadIdx.x;
    const int lane = tid & 31;
    const int wid  = tid >> 5;
    const int wm   = wid >> 2;
    const int wn   = wid & 3;

    const uint32_t sbase = smem_u32(sm);

    const int aRow = wm * 64 + (lane & 7) + ((lane >> 3) & 1) * 8;
    const uint32_t aOff = (uint32_t)(aRow * 72 + ((lane >> 4) & 1) * 8) * 2;
    const int bRow = wn * 32 + (lane & 7) + ((lane >> 4) & 1) * 8;
    const uint32_t bOff = (uint32_t)(bRow * 72 + ((lane >> 3) & 1) * 8) * 2;

    // loader: 128 rows x 64 halves per operand; 1024 cp16 each; 8 cp16/thread
    auto issue = [&](int c) {
        const int k0 = c << 6;
        const uint32_t st = sbase + (uint32_t)(c % 3) * STGB;
        #pragma unroll
        for (int i = 0; i < 4; i++) {
            int op = tid + i * 256;          // 0..1023
            int row = op >> 3, c8 = (op & 7) * 8;
            uint32_t d = st + (uint32_t)(row * 72 + c8) * 2;
            cp16(d,           A + (long)row * lda + k0 + c8);
            cp16(d + 18432,   B + (long)row * ldb + k0 + c8);
        }
    };

    auto compute = [&](int c) {
        const uint32_t As = sbase + (uint32_t)(c % 3) * STGB;
        const uint32_t Bs = As + 18432;
        #pragma unroll
        for (int ks = 0; ks < 4; ks++) {
            uint32_t ah[4][4], bh[4][2];
            #pragma unroll
            for (int mt = 0; mt < 4; mt++)
                ldsm4(ah[mt], As + aOff + (uint32_t)(mt * 16 * 72 + ks * 16) * 2);
            #pragma unroll
            for (int np = 0; np < 2; np++) {
                uint32_t raw[4];
                ldsm4(raw, Bs + bOff + (uint32_t)(np * 16 * 72 + ks * 16) * 2);
                bh[np * 2][0] = raw[0]; bh[np * 2][1] = raw[1];
                bh[np * 2 + 1][0] = raw[2]; bh[np * 2 + 1][1] = raw[3];
            }
            #pragma unroll
            for (int mt = 0; mt < 4; mt++)
                #pragma unroll
                for (int nt = 0; nt < 4; nt++)
                    mma_f16(acc[mt][nt], ah[mt], bh[nt]);
        }
    };

    const int NC = K >> 6;                   // K/64 >= 1
    issue(0); CP_COMMIT();
    if (1 < NC) issue(1);
    CP_COMMIT();
    for (int c = 0; c < NC; c++) {
        CP_WAIT1();                          // groups retire in order -> chunk c done
        __syncthreads();
        if (c + 2 < NC) issue(c + 2);
        CP_COMMIT();
        compute(c);
    }
    CP_WAIT0();                              // drain before smem reuse
    __syncthreads();
}

// ======= staged epilogue: acc -> SMEM -> coalesced 16B GMEM stores =============
// OUTH=1: half out, smem pitch 136 halves; OUTH=0: float out, smem pitch 132 fl.
template<int OUTH>
__device__ __forceinline__ void gemm_epi(
    void* __restrict__ Cv, int ldc, int m0, int n0, float (*acc)[4][4], char* sm)
{
    const int tid  = threadIdx.x;
    const int lane = tid & 31;
    const int wid  = tid >> 5;
    const int gid  = lane >> 2;
    const int tig  = lane & 3;
    const int wm   = wid >> 2;
    const int wn   = wid & 3;

    if (OUTH) {
        __half* ts = (__half*)sm;
        #pragma unroll
        for (int mt = 0; mt < 4; mt++) {
            #pragma unroll
            for (int nt = 0; nt < 4; nt++) {
                int r  = wm * 64 + mt * 16 + gid;
                int cc = wn * 32 + nt * 8 + tig * 2;
                *(__half2*)&ts[r * 136 + cc] =
                    __floats2half2_rn(acc[mt][nt][0], acc[mt][nt][1]);
                *(__half2*)&ts[(r + 8) * 136 + cc] =
                    __floats2half2_rn(acc[mt][nt][2], acc[mt][nt][3]);
            }
        }
        __syncthreads();
        __half* C = (__half*)Cv + (long)m0 * ldc + n0;
        #pragma unroll
        for (int i = 0; i < 8; i++) {
            int idx = tid + i * 256;         // 0..2047
            int row = idx >> 4, c16 = idx & 15;
            uint4 v = *(const uint4*)&ts[row * 136 + c16 * 8];
            *(uint4*)&C[(long)row * ldc + c16 * 8] = v;
        }
    } else {
        float* ts = (float*)sm;
        #pragma unroll
        for (int mt = 0; mt < 4; mt++) {
            #pragma unroll
            for (int nt = 0; nt < 4; nt++) {
                int r  = wm * 64 + mt * 16 + gid;
                int cc = wn * 32 + nt * 8 + tig * 2;
                *(float2*)&ts[r * 132 + cc] =
                    make_float2(acc[mt][nt][0], acc[mt][nt][1]);
                *(float2*)&ts[(r + 8) * 132 + cc] =
                    make_float2(acc[mt][nt][2], acc[mt][nt][3]);
            }
        }
        __syncthreads();
        float* C = (float*)Cv + (long)m0 * ldc + n0;
        #pragma unroll
        for (int i = 0; i < 16; i++) {
            int idx = tid + i * 256;         // 0..4095
            int row = idx >> 5, c4 = idx & 31;
            uint4 v = *(const uint4*)&ts[row * 132 + c4 * 4];
            *(uint4*)&C[(long)row * ldc + c4 * 4] = v;
        }
    }
    __syncthreads();
}

#define ACC_INIT(acc) { _Pragma("unroll") for (int _m = 0; _m < 4; _m++) \
    _Pragma("unroll") for (int _n = 0; _n < 4; _n++) \
    _Pragma("unroll") for (int _i = 0; _i < 4; _i++) acc[_m][_n][_i] = 0.0f; }

// generic batched fp16 GEMM; kclip limits K causally (128-grain, mult of 64)
template<int OUTH>
__global__ void __launch_bounds__(256, 2)
gemm_h(const __half* __restrict__ Ab, const __half* __restrict__ Bb, void* __restrict__ Cb,
       int K, int lda, int ldb, int ldc,
       int zInner, long sAo, long sAi, long sBo, long sBi, long sCo, long sCi,
       const int* offset_p, int kclip)
{
    extern __shared__ char smc[];
    const int z  = blockIdx.z;
    const int zo = z / zInner, zi = z % zInner;
    const int m0 = blockIdx.y * 128;
    const int n0 = blockIdx.x * 128;
    if (kclip) {
        int lim = m0 + 128 + *offset_p;
        lim = (lim + 127) & ~127;
        if (lim < K) K = lim;
    }
    float acc[4][4][4];
    ACC_INIT(acc);
    gemm_tiles_h(Ab + zo * sAo + zi * sAi + (long)m0 * lda,
                 Bb + zo * sBo + zi * sBi + (long)n0 * ldb,
                 K, lda, ldb, acc, smc);
    if (OUTH)
        gemm_epi<1>((__half*)Cb + zo * sCo + zi * sCi, ldc, m0, n0, acc, smc);
    else
        gemm_epi<0>((float*)Cb + zo * sCo + zi * sCi, ldc, m0, n0, acc, smc);
}

// fused triple projection (half out): ckv 4 | krope 8 | q 24 blocks of 128
__global__ void __launch_bounds__(256, 2)
gemm_proj3(const __half* __restrict__ x,
           const __half* __restrict__ Wdkv, const __half* __restrict__ Wkr,
           const __half* __restrict__ Wq,
           __half* __restrict__ ckv, __half* __restrict__ krope, __half* __restrict__ q)
{
    extern __shared__ char smc[];
    const int bx = blockIdx.x;
    const __half* B; __half* C; int ldc, n0;
    if (bx < 4)       { B = Wdkv; C = ckv;   ldc = LL;       n0 = bx * 128; }
    else if (bx < 12) { B = Wkr;  C = krope; ldc = HH * RD;  n0 = (bx - 4) * 128; }
    else              { B = Wq;   C = q;     ldc = QW;       n0 = (bx - 12) * 128; }
    const int m0 = blockIdx.y * 128;
    float acc[4][4][4];
    ACC_INIT(acc);
    gemm_tiles_h(x + (long)m0 * DIN, B + (long)n0 * DIN, DIN, DIN, DIN, acc, smc);
    gemm_epi<1>(C, ldc, m0, n0, acc, smc);
}

// fused scores: rope (K=64) + latent (K=512), causal block skip, half out
__global__ void __launch_bounds__(256, 2)
gemm_scores(const __half* __restrict__ q, const __half* __restrict__ krope,
            const __half* __restrict__ qabs, const __half* __restrict__ ckv,
            __half* __restrict__ scores, const int* __restrict__ offset_p)
{
    extern __shared__ char smc[];
    const int m0 = blockIdx.y * 128;
    const int n0 = blockIdx.x * 128;
    if (n0 > m0 + 127 + *offset_p) return;
    const int b = blockIdx.z >> 4;
    const int h = blockIdx.z & 15;

    float acc[4][4][4];
    ACC_INIT(acc);

    const __half* A1 = q + (long)b * SS * QW + DOUT + h * RD + (long)m0 * QW;
    const __half* B1 = krope + (long)b * SS * (HH * RD) + h * RD + (long)n0 * (HH * RD);
    gemm_tiles_h(A1, B1, RD, QW, HH * RD, acc, smc);

    const __half* A2 = qabs + (long)b * SS * (HH * LL) + h * LL + (long)m0 * (HH * LL);
    const __half* B2 = ckv + (long)b * SS * LL + (long)n0 * LL;
    gemm_tiles_h(A2, B2, LL, HH * LL, LL, acc, smc);

    gemm_epi<1>(scores + (long)blockIdx.z * SS * TT, TT, m0, n0, acc, smc);
}

// ================= small kernels ===============================================
// one kernel, six fp32->fp16 segments (float4 granularity)
__global__ void halfify_all(
    const float* s0, __half* d0, int n0,
    const float* s1, __half* d1, int n1,
    const float* s2, __half* d2, int n2,
    const float* s3, __half* d3, int n3,
    const float* s4, __half* d4, int n4,
    const float* s5, __half* d5, int n5)
{
    long i = (long)blockIdx.x * blockDim.x + threadIdx.x;
    const float* s; __half* d;
    if (i < n0)              { s = s0; d = d0; }
    else if ((i -= n0) < n1) { s = s1; d = d1; }
    else if ((i -= n1) < n2) { s = s2; d = d2; }
    else if ((i -= n2) < n3) { s = s3; d = d3; }
    else if ((i -= n3) < n4) { s = s4; d = d4; }
    else if ((i -= n4) < n5) { s = s5; d = d5; }
    else return;
    float4 v = ((const float4*)s)[i];
    __half2* o = (__half2*)d;
    o[i * 2]     = __floats2half2_rn(v.x, v.y);
    o[i * 2 + 1] = __floats2half2_rn(v.z, v.w);
}

__global__ void rmsnorm_kernel(__half* __restrict__ data, const float* __restrict__ w)
{
    const int row = blockIdx.x;
    __half* p = data + (long)row * LL;
    float ss = 0.0f;
    float vals[4];
    #pragma unroll
    for (int i = 0; i < 4; i++) {
        vals[i] = __half2float(p[threadIdx.x + i * 128]);
        ss += vals[i] * vals[i];
    }
    __shared__ float red[32];
    for (int o = 16; o; o >>= 1) ss += __shfl_xor_sync(0xffffffffu, ss, o);
    if ((threadIdx.x & 31) == 0) red[threadIdx.x >> 5] = ss;
    __syncthreads();
    if (threadIdx.x < 32) {
        float v = (threadIdx.x < 4) ? red[threadIdx.x] : 0.0f;
        for (int o = 16; o; o >>= 1) v += __shfl_xor_sync(0xffffffffu, v, o);
        if (threadIdx.x == 0) red[0] = v;
    }
    __syncthreads();
    float rstd = rsqrtf(red[0] / (float)LL + 1e-6f);
    #pragma unroll
    for (int i = 0; i < 4; i++)
        p[threadIdx.x + i * 128] = __float2half_rn(vals[i] * rstd * w[threadIdx.x + i * 128]);
}

// both rope applications in one launch
__global__ void rope_both(__half* __restrict__ krope, __half* __restrict__ q,
                          const int* __restrict__ offset_p)
{
    const long per = (long)ROWS * HH * HALF_RD;
    long idx = (long)blockIdx.x * blockDim.x + threadIdx.x;
    __half* data; int ld, colbase;
    if (idx < per) { data = krope; ld = HH * RD; colbase = 0; }
    else if ((idx -= per) < per) { data = q; ld = QW; colbase = DOUT; }
    else return;
    int  j   = (int)(idx % HALF_RD);
    int  h   = (int)((idx / HALF_RD) % HH);
    long row = idx / (HALF_RD * HH);
    int  s   = (int)(row % SS);
    float pos = (float)(s + *offset_p);
    float inv = expf(-(float)j * (logf(10000.0f) / 32.0f));
    float ang = pos * inv;
    float c  = cosf(ang);
    float si = sinf(ang);
    __half* p = data + row * (long)ld + colbase + h * RD;
    float x1 = __half2float(p[j]), x2 = __half2float(p[j + HALF_RD]);
    p[j]           = __float2half_rn(x1 * c - x2 * si);
    p[j + HALF_RD] = __float2half_rn(x2 * c + x1 * si);
}

// masked scaled softmax; half scores in, half probs out; zero-fill to 128-grain
__global__ void __launch_bounds__(256)
softmax_kernel(const __half* __restrict__ scores, __half* __restrict__ probs,
               const int* __restrict__ offset_p)
{
    const long row = blockIdx.x;            // (b*H+h)*S + s
    const int  s   = (int)(row % SS);
    const int  off = *offset_p;
    int valid = s + off + 1;
    if (valid > TT) valid = TT;
    int limit = ((s & ~127) + 128 + off + 127) & ~127;
    if (limit > TT) limit = TT;
    const __half* p = scores + row * (long)TT;
    __half* op = probs + row * (long)TT;
    const float scale = rsqrtf((float)(HD + RD));
    const int tid = threadIdx.x;
    const int e0 = tid * 8;

    float f[8];
    float m = -INFINITY;
    if (e0 < valid) {
        uint4 raw = *(const uint4*)(p + e0);
        const __half2* hp = (const __half2*)&raw;
        #pragma unroll
        for (int j = 0; j < 4; j++) {
            float2 v2 = __half22float2(hp[j]);
            f[j * 2]     = (e0 + j * 2 < valid)     ? v2.x * scale : -INFINITY;
            f[j * 2 + 1] = (e0 + j * 2 + 1 < valid) ? v2.y * scale : -INFINITY;
        }
        #pragma unroll
        for (int j = 0; j < 8; j++) m = fmaxf(m, f[j]);
    } else {
        #pragma unroll
        for (int j = 0; j < 8; j++) f[j] = -INFINITY;
    }

    __shared__ float red[32];
    for (int o = 16; o; o >>= 1) m = fmaxf(m, __shfl_xor_sync(0xffffffffu, m, o));
    if ((tid & 31) == 0) red[tid >> 5] = m;
    __syncthreads();
    if (tid < 32) {
        float t = (tid < 8) ? red[tid] : -INFINITY;
        for (int o = 16; o; o >>= 1) t = fmaxf(t, __shfl_xor_sync(0xffffffffu, t, o));
        if (tid == 0) red[0] = t;
    }
    __syncthreads();
    m = red[0];
    __syncthreads();

    float sum = 0.0f;
    #pragma unroll
    for (int j = 0; j < 8; j++) {
        float e = (f[j] == -INFINITY) ? 0.0f : expf(f[j] - m);
        f[j] = e;
        sum += e;
    }
    for (int o = 16; o; o >>= 1) sum += __shfl_xor_sync(0xffffffffu, sum, o);
    if ((tid & 31) == 0) red[tid >> 5] = sum;
    __syncthreads();
    if (tid < 32) {
        float t = (tid < 8) ? red[tid] : 0.0f;
        for (int o = 16; o; o >>= 1) t += __shfl_xor_sync(0xffffffffu, t, o);
        if (tid == 0) red[0] = t;
    }
    __syncthreads();
    float inv = 1.0f / red[0];

    if (e0 < limit) {
        uint4 outv;
        __half2* ho = (__half2*)&outv;
        #pragma unroll
        for (int j = 0; j < 4; j++)
            ho[j] = __floats2half2_rn(f[j * 2] * inv, f[j * 2 + 1] * inv);
        *(uint4*)(op + e0) = outv;
    }
}

// half->half 32x32 transpose, batched over z
__global__ void transpose_h(const __half* __restrict__ in, __half* __restrict__ out,
                            int R, int Cc, long sIn, long sOut)
{
    __shared__ __half t[32][33];
    const __half* ip = in + blockIdx.z * sIn;
    __half* op = out + blockIdx.z * sOut;
    const int c0 = blockIdx.x * 32, r0 = blockIdx.y * 32;
    for (int i = threadIdx.y; i < 32; i += 8)
        t[i][threadIdx.x] = ip[(long)(r0 + i) * Cc + c0 + threadIdx.x];
    __syncthreads();
    for (int i = threadIdx.y; i < 32; i += 8)
        op[(long)(c0 + i) * R + r0 + threadIdx.x] = t[threadIdx.x][i];
}

// float->half 32x32 transpose, batched over z (for W_UK)
__global__ void transpose_f2h(const float* __restrict__ in, __half* __restrict__ out,
                              int R, int Cc, long sIn, long sOut)
{
    __shared__ __half t[32][33];
    const float* ip = in + blockIdx.z * sIn;
    __half* op = out + blockIdx.z * sOut;
    const int c0 = blockIdx.x * 32, r0 = blockIdx.y * 32;
    for (int i = threadIdx.y; i < 32; i += 8)
        t[i][threadIdx.x] = __float2half_rn(ip[(long)(r0 + i) * Cc + c0 + threadIdx.x]);
    __syncthreads();
    for (int i = threadIdx.y; i < 32; i += 8)
        op[(long)(c0 + i) * R + r0 + threadIdx.x] = t[threadIdx.x][i];
}

// ================= host side ====================================================
template<typename T>
static T* sym_addr(const void* sym)
{
    void* p = nullptr;
    cudaGetSymbolAddress(&p, sym);
    return (T*)p;
}

extern "C" void kernel_launch(void* const* d_in, const int* in_sizes, int n_in,
                              void* d_out, int out_size)
{
    const float* x       = (const float*)d_in[0];
    const float* W_DKV   = (const float*)d_in[1];
    const float* W_KRope = (const float*)d_in[2];
    const float* W_Q     = (const float*)d_in[3];
    const float* W_UK    = (const float*)d_in[4];
    const float* W_UV    = (const float*)d_in[5];
    const float* W_O     = (const float*)d_in[6];
    const float* kvw     = (const float*)d_in[7];
    const int*   offset  = (const int*)d_in[8];
    float* out = (float*)d_out;

    static int s_init = 0;
    if (!s_init) {
        cudaFuncSetAttribute((const void*)gemm_h<0>, cudaFuncAttributeMaxDynamicSharedMemorySize, GEMM_SMEM);
        cudaFuncSetAttribute((const void*)gemm_h<1>, cudaFuncAttributeMaxDynamicSharedMemorySize, GEMM_SMEM);
        cudaFuncSetAttribute((const void*)gemm_proj3, cudaFuncAttributeMaxDynamicSharedMemorySize, GEMM_SMEM);
        cudaFuncSetAttribute((const void*)gemm_scores, cudaFuncAttributeMaxDynamicSharedMemorySize, GEMM_SMEM);
        s_init = 1;
    }

    __half* x16    = sym_addr<__half>(g_x16);
    __half* wdkv16 = sym_addr<__half>(g_wdkv16);
    __half* wkr16  = sym_addr<__half>(g_wkr16);
    __half* wq16   = sym_addr<__half>(g_wq16);
    __half* wo16   = sym_addr<__half>(g_wo16);
    __half* wuv16  = sym_addr<__half>(g_wuv16);
    __half* ckv16  = sym_addr<__half>(g_ckv16);
    __half* ckvT16 = sym_addr<__half>(g_ckvT16);
    __half* krope16= sym_addr<__half>(g_krope16);
    __half* q16    = sym_addr<__half>(g_q16);
    __half* qabs16 = sym_addr<__half>(g_qabs16);
    __half* wukT16 = sym_addr<__half>(g_wukT16);
    __half* scores16 = sym_addr<__half>(g_scores16);
    __half* probs16  = sym_addr<__half>(g_probs16);
    __half* ctxlat16 = sym_addr<__half>(g_ctxlat16);
    __half* ctx16  = sym_addr<__half>(g_ctx16);

    // 0) half-round all six fp32 inputs in ONE launch
    {
        const int nx = ROWS*DIN/4, n1 = LL*DIN/4, n2 = HH*RD*DIN/4;
        const int n3 = QW*DIN/4, n4 = DIN*DOUT/4, n5 = DOUT*LL/4;
        long total = (long)nx + n1 + n2 + n3 + n4 + n5;
        halfify_all<<<(int)((total + 255) / 256), 256>>>(
            x, x16, nx, W_DKV, wdkv16, n1, W_KRope, wkr16, n2,
            W_Q, wq16, n3, W_O, wo16, n4, W_UV, wuv16, n5);
    }

    // 1-3) fused projections
    {
        dim3 grid(36, 32, 1);
        gemm_proj3<<<grid, 256, GEMM_SMEM>>>(x16, wdkv16, wkr16, wq16,
                                             ckv16, krope16, q16);
    }
    rmsnorm_kernel<<<ROWS, 128>>>(ckv16, kvw);
    {
        dim3 grid(LL / 32, SS / 32, BB), block(32, 8);
        transpose_h<<<grid, block>>>(ckv16, ckvT16, SS, LL,
                                     (long)SS * LL, (long)LL * SS);
    }
    {
        long total = 2L * ROWS * HH * HALF_RD;
        rope_both<<<(int)((total + 255) / 256), 256>>>(krope16, q16, offset);
    }

    // W_UK^T per head (fp32 -> half)
    {
        dim3 grid(LL / 32, HD / 32, HH), block(32, 8);
        transpose_f2h<<<grid, block>>>(W_UK, wukT16, HD, LL,
                                       (long)HD * LL, (long)LL * HD);
    }

    // 4) q_abs (half out)
    {
        dim3 grid(LL / 128, ROWS / 128, HH);
        gemm_h<1><<<grid, 256, GEMM_SMEM>>>(q16, wukT16, qabs16,
            HD, QW, HD, HH * LL,
            HH, 0, HD, 0, (long)LL * HD, 0, LL, nullptr, 0);
    }

    // 5) fused scores (causal block skip), half out
    {
        dim3 grid(TT / 128, SS / 128, BB * HH);
        gemm_scores<<<grid, 256, GEMM_SMEM>>>(q16, krope16, qabs16, ckv16,
                                              scores16, offset);
    }

    // 6) softmax: half scores -> half probs
    softmax_kernel<<<BB * HH * SS, 256>>>(scores16, probs16, offset);

    // 7) ctx_lat = probs @ ckvT (K clipped causally), half out
    {
        dim3 grid(LL / 128, SS / 128, BB * HH);
        gemm_h<1><<<grid, 256, GEMM_SMEM>>>(probs16, ckvT16, ctxlat16,
            TT, TT, SS, HH * LL,
            HH, (long)HH * SS * TT, (long)SS * TT,
            (long)LL * SS, 0,
            (long)SS * HH * LL, LL, offset, 1);
    }

    // 8) ctx = ctxlat @ W_UV^T per head (fp16, half out)
    {
        dim3 grid(HD / 128, ROWS / 128, HH);
        gemm_h<1><<<grid, 256, GEMM_SMEM>>>(ctxlat16, wuv16, ctx16,
            LL, HH * LL, LL, DOUT,
            HH, 0, LL, 0, (long)HD * LL, 0, HD, nullptr, 0);
    }

    // 9) out = ctx @ W_O^T (fp32 out, staged coalesced)
    {
        dim3 grid(DIN / 128, ROWS / 128, 1);
        gemm_h<0><<<grid, 256, GEMM_SMEM>>>(ctx16, wo16, out,
            DOUT, DOUT, DOUT, DIN,
            1, 0, 0, 0, 0, 0, 0, nullptr, 0);
    }
}

// round 14
// speedup vs baseline: 1.6488x; 1.1604x over previous
#include <cuda_runtime.h>
#include <cuda_fp16.h>
#include <math.h>
#include <stdint.h>

// Problem constants
#define BB 2
#define SS 2048
#define TT 2048
#define DIN 2048
#define DOUT 2048
#define HH 16
#define RD 64
#define HALF_RD 32
#define LL 512
#define HD 128
#define ROWS (BB*SS)          // 4096
#define QW (DOUT+HH*RD)       // 3072

// ---------------- device scratch (static; no allocations) ---------------------
__device__ __align__(128) __half g_x16  [ROWS*DIN];
__device__ __align__(128) __half g_wdkv16[LL*DIN];
__device__ __align__(128) __half g_wkr16 [HH*RD*DIN];
__device__ __align__(128) __half g_wq16  [QW*DIN];
__device__ __align__(128) __half g_wo16  [DIN*DOUT];
__device__ __align__(128) __half g_wuv16 [DOUT*LL];
__device__ __align__(128) __half g_wuk16 [DOUT*LL];
__device__ __align__(128) __half g_ckv16 [BB*SS*LL];
__device__ __align__(128) __half g_ckvT16[BB*LL*SS];
__device__ __align__(128) __half g_krope16[BB*SS*HH*RD];
__device__ __align__(128) __half g_q16   [BB*SS*QW];
__device__ __align__(128) __half g_m2t16 [(long)BB*HH*TT*HD];   // [b,h][t,d]
__device__ __align__(128) __half g_scores16[(long)BB*HH*SS*TT];
__device__ __align__(128) __half g_probs16 [(long)BB*HH*SS*TT];
__device__ __align__(128) __half g_ctxlat16[ROWS*HH*LL];
__device__ __align__(128) __half g_ctx16 [ROWS*DOUT];

// ================= helpers =====================================================
__device__ __forceinline__ uint32_t smem_u32(const void* p) {
    uint32_t a;
    asm("{ .reg .u64 t; cvta.to.shared.u64 t, %1; cvt.u32.u64 %0, t; }" : "=r"(a) : "l"(p));
    return a;
}
__device__ __forceinline__ void cp16(uint32_t dst, const void* src) {
    asm volatile("cp.async.cg.shared.global [%0], [%1], 16;" :: "r"(dst), "l"(src));
}
#define CP_COMMIT() asm volatile("cp.async.commit_group;" ::: "memory")
#define CP_WAIT1()  asm volatile("cp.async.wait_group 1;"  ::: "memory")
#define CP_WAIT0()  asm volatile("cp.async.wait_group 0;"  ::: "memory")

__device__ __forceinline__ void ldsm4(uint32_t* r, uint32_t addr) {
    asm volatile("ldmatrix.sync.aligned.m8n8.x4.shared.b16 {%0,%1,%2,%3}, [%4];"
                 : "=r"(r[0]), "=r"(r[1]), "=r"(r[2]), "=r"(r[3]) : "r"(addr));
}
__device__ __forceinline__ void mma_f16(float* c, const uint32_t* a, const uint32_t* b) {
    asm volatile(
        "mma.sync.aligned.m16n8k16.row.col.f32.f16.f16.f32 "
        "{%0,%1,%2,%3}, {%4,%5,%6,%7}, {%8,%9}, {%0,%1,%2,%3};"
        : "+f"(c[0]), "+f"(c[1]), "+f"(c[2]), "+f"(c[3])
        : "r"(a[0]), "r"(a[1]), "r"(a[2]), "r"(a[3]), "r"(b[0]), "r"(b[1]));
}

// ================= FP16 GEMM tile engine: 128x128, K-chunk 64, 3 stages =========
#define STGB 36864
#define GEMM_SMEM (3*STGB)      // 110592 B; x2 CTA = 216 KB <= 228 KB

__device__ __forceinline__ void gemm_tiles_h(
    const __half* __restrict__ A, const __half* __restrict__ B,
    int K, int lda, int ldb, float (*acc)[4][4], char* sm)
{
    const int tid  = threadIdx.x;
    const int lane = tid & 31;
    const int wid  = tid >> 5;
    const int wm   = wid >> 2;
    const int wn   = wid & 3;

    const uint32_t sbase = smem_u32(sm);

    const int aRow = wm * 64 + (lane & 7) + ((lane >> 3) & 1) * 8;
    const uint32_t aOff = (uint32_t)(aRow * 72 + ((lane >> 4) & 1) * 8) * 2;
    const int bRow = wn * 32 + (lane & 7) + ((lane >> 4) & 1) * 8;
    const uint32_t bOff = (uint32_t)(bRow * 72 + ((lane >> 3) & 1) * 8) * 2;

    auto issue = [&](int c) {
        const int k0 = c << 6;
        const uint32_t st = sbase + (uint32_t)(c % 3) * STGB;
        #pragma unroll
        for (int i = 0; i < 4; i++) {
            int op = tid + i * 256;
            int row = op >> 3, c8 = (op & 7) * 8;
            uint32_t d = st + (uint32_t)(row * 72 + c8) * 2;
            cp16(d,           A + (long)row * lda + k0 + c8);
            cp16(d + 18432,   B + (long)row * ldb + k0 + c8);
        }
    };

    auto compute = [&](int c) {
        const uint32_t As = sbase + (uint32_t)(c % 3) * STGB;
        const uint32_t Bs = As + 18432;
        #pragma unroll
        for (int ks = 0; ks < 4; ks++) {
            uint32_t ah[4][4], bh[4][2];
            #pragma unroll
            for (int mt = 0; mt < 4; mt++)
                ldsm4(ah[mt], As + aOff + (uint32_t)(mt * 16 * 72 + ks * 16) * 2);
            #pragma unroll
            for (int np = 0; np < 2; np++) {
                uint32_t raw[4];
                ldsm4(raw, Bs + bOff + (uint32_t)(np * 16 * 72 + ks * 16) * 2);
                bh[np * 2][0] = raw[0]; bh[np * 2][1] = raw[1];
                bh[np * 2 + 1][0] = raw[2]; bh[np * 2 + 1][1] = raw[3];
            }
            #pragma unroll
            for (int mt = 0; mt < 4; mt++)
                #pragma unroll
                for (int nt = 0; nt < 4; nt++)
                    mma_f16(acc[mt][nt], ah[mt], bh[nt]);
        }
    };

    const int NC = K >> 6;
    issue(0); CP_COMMIT();
    if (1 < NC) issue(1);
    CP_COMMIT();
    for (int c = 0; c < NC; c++) {
        CP_WAIT1();
        __syncthreads();
        if (c + 2 < NC) issue(c + 2);
        CP_COMMIT();
        compute(c);
    }
    CP_WAIT0();
    __syncthreads();
}

// ======= staged epilogue: acc -> SMEM -> coalesced 16B GMEM stores =============
template<int OUTH>
__device__ __forceinline__ void gemm_epi(
    void* __restrict__ Cv, int ldc, int m0, int n0, float (*acc)[4][4], char* sm)
{
    const int tid  = threadIdx.x;
    const int lane = tid & 31;
    const int wid  = tid >> 5;
    const int gid  = lane >> 2;
    const int tig  = lane & 3;
    const int wm   = wid >> 2;
    const int wn   = wid & 3;

    if (OUTH) {
        __half* ts = (__half*)sm;
        #pragma unroll
        for (int mt = 0; mt < 4; mt++) {
            #pragma unroll
            for (int nt = 0; nt < 4; nt++) {
                int r  = wm * 64 + mt * 16 + gid;
                int cc = wn * 32 + nt * 8 + tig * 2;
                *(__half2*)&ts[r * 136 + cc] =
                    __floats2half2_rn(acc[mt][nt][0], acc[mt][nt][1]);
                *(__half2*)&ts[(r + 8) * 136 + cc] =
                    __floats2half2_rn(acc[mt][nt][2], acc[mt][nt][3]);
            }
        }
        __syncthreads();
        __half* C = (__half*)Cv + (long)m0 * ldc + n0;
        #pragma unroll
        for (int i = 0; i < 8; i++) {
            int idx = tid + i * 256;
            int row = idx >> 4, c16 = idx & 15;
            uint4 v = *(const uint4*)&ts[row * 136 + c16 * 8];
            *(uint4*)&C[(long)row * ldc + c16 * 8] = v;
        }
    } else {
        float* ts = (float*)sm;
        #pragma unroll
        for (int mt = 0; mt < 4; mt++) {
            #pragma unroll
            for (int nt = 0; nt < 4; nt++) {
                int r  = wm * 64 + mt * 16 + gid;
                int cc = wn * 32 + nt * 8 + tig * 2;
                *(float2*)&ts[r * 132 + cc] =
                    make_float2(acc[mt][nt][0], acc[mt][nt][1]);
                *(float2*)&ts[(r + 8) * 132 + cc] =
                    make_float2(acc[mt][nt][2], acc[mt][nt][3]);
            }
        }
        __syncthreads();
        float* C = (float*)Cv + (long)m0 * ldc + n0;
        #pragma unroll
        for (int i = 0; i < 16; i++) {
            int idx = tid + i * 256;
            int row = idx >> 5, c4 = idx & 31;
            uint4 v = *(const uint4*)&ts[row * 132 + c4 * 4];
            *(uint4*)&C[(long)row * ldc + c4 * 4] = v;
        }
    }
    __syncthreads();
}

#define ACC_INIT(acc) { _Pragma("unroll") for (int _m = 0; _m < 4; _m++) \
    _Pragma("unroll") for (int _n = 0; _n < 4; _n++) \
    _Pragma("unroll") for (int _i = 0; _i < 4; _i++) acc[_m][_n][_i] = 0.0f; }

// generic batched fp16 GEMM; kclip limits K causally (128-grain, mult of 64)
template<int OUTH>
__global__ void __launch_bounds__(256, 2)
gemm_h(const __half* __restrict__ Ab, const __half* __restrict__ Bb, void* __restrict__ Cb,
       int K, int lda, int ldb, int ldc,
       int zInner, long sAo, long sAi, long sBo, long sBi, long sCo, long sCi,
       const int* offset_p, int kclip)
{
    extern __shared__ char smc[];
    const int z  = blockIdx.z;
    const int zo = z / zInner, zi = z % zInner;
    const int m0 = blockIdx.y * 128;
    const int n0 = blockIdx.x * 128;
    if (kclip) {
        int lim = m0 + 128 + *offset_p;
        lim = (lim + 127) & ~127;
        if (lim < K) K = lim;
    }
    float acc[4][4][4];
    ACC_INIT(acc);
    gemm_tiles_h(Ab + zo * sAo + zi * sAi + (long)m0 * lda,
                 Bb + zo * sBo + zi * sBi + (long)n0 * ldb,
                 K, lda, ldb, acc, smc);
    if (OUTH)
        gemm_epi<1>((__half*)Cb + zo * sCo + zi * sCi, ldc, m0, n0, acc, smc);
    else
        gemm_epi<0>((float*)Cb + zo * sCo + zi * sCi, ldc, m0, n0, acc, smc);
}

// fused triple projection (half out): ckv 4 | krope 8 | q 24 blocks of 128
__global__ void __launch_bounds__(256, 2)
gemm_proj3(const __half* __restrict__ x,
           const __half* __restrict__ Wdkv, const __half* __restrict__ Wkr,
           const __half* __restrict__ Wq,
           __half* __restrict__ ckv, __half* __restrict__ krope, __half* __restrict__ q)
{
    extern __shared__ char smc[];
    const int bx = blockIdx.x;
    const __half* B; __half* C; int ldc, n0;
    if (bx < 4)       { B = Wdkv; C = ckv;   ldc = LL;       n0 = bx * 128; }
    else if (bx < 12) { B = Wkr;  C = krope; ldc = HH * RD;  n0 = (bx - 4) * 128; }
    else              { B = Wq;   C = q;     ldc = QW;       n0 = (bx - 12) * 128; }
    const int m0 = blockIdx.y * 128;
    float acc[4][4][4];
    ACC_INIT(acc);
    gemm_tiles_h(x + (long)m0 * DIN, B + (long)n0 * DIN, DIN, DIN, DIN, acc, smc);
    gemm_epi<1>(C, ldc, m0, n0, acc, smc);
}

// fused scores: rope (K=64) + absorbed latent (K=128 via M2T), causal skip
__global__ void __launch_bounds__(256, 2)
gemm_scores(const __half* __restrict__ q, const __half* __restrict__ krope,
            const __half* __restrict__ m2t,
            __half* __restrict__ scores, const int* __restrict__ offset_p)
{
    extern __shared__ char smc[];
    const int m0 = blockIdx.y * 128;
    const int n0 = blockIdx.x * 128;
    if (n0 > m0 + 127 + *offset_p) return;
    const int b = blockIdx.z >> 4;
    const int h = blockIdx.z & 15;

    float acc[4][4][4];
    ACC_INIT(acc);

    // rope part: q_rope[s,:RD] . krope[t,:RD]
    const __half* A1 = q + (long)b * SS * QW + DOUT + h * RD + (long)m0 * QW;
    const __half* B1 = krope + (long)b * SS * (HH * RD) + h * RD + (long)n0 * (HH * RD);
    gemm_tiles_h(A1, B1, RD, QW, HH * RD, acc, smc);

    // absorbed latent part: q_content[s,:HD] . M2T[t,:HD]   (K=128)
    const __half* A2 = q + (long)b * SS * QW + h * HD + (long)m0 * QW;
    const __half* B2 = m2t + (long)blockIdx.z * TT * HD + (long)n0 * HD;
    gemm_tiles_h(A2, B2, HD, QW, HD, acc, smc);

    gemm_epi<1>(scores + (long)blockIdx.z * SS * TT, TT, m0, n0, acc, smc);
}

// ================= small kernels ===============================================
// one kernel, seven fp32->fp16 segments (float4 granularity)
__global__ void halfify_all(
    const float* s0, __half* d0, int n0,
    const float* s1, __half* d1, int n1,
    const float* s2, __half* d2, int n2,
    const float* s3, __half* d3, int n3,
    const float* s4, __half* d4, int n4,
    const float* s5, __half* d5, int n5,
    const float* s6, __half* d6, int n6)
{
    long i = (long)blockIdx.x * blockDim.x + threadIdx.x;
    const float* s; __half* d;
    if (i < n0)              { s = s0; d = d0; }
    else if ((i -= n0) < n1) { s = s1; d = d1; }
    else if ((i -= n1) < n2) { s = s2; d = d2; }
    else if ((i -= n2) < n3) { s = s3; d = d3; }
    else if ((i -= n3) < n4) { s = s4; d = d4; }
    else if ((i -= n4) < n5) { s = s5; d = d5; }
    else if ((i -= n5) < n6) { s = s6; d = d6; }
    else return;
    float4 v = ((const float4*)s)[i];
    __half2* o = (__half2*)d;
    o[i * 2]     = __floats2half2_rn(v.x, v.y);
    o[i * 2 + 1] = __floats2half2_rn(v.z, v.w);
}

__global__ void rmsnorm_kernel(__half* __restrict__ data, const float* __restrict__ w)
{
    const int row = blockIdx.x;
    __half* p = data + (long)row * LL;
    float ss = 0.0f;
    float vals[4];
    #pragma unroll
    for (int i = 0; i < 4; i++) {
        vals[i] = __half2float(p[threadIdx.x + i * 128]);
        ss += vals[i] * vals[i];
    }
    __shared__ float red[32];
    for (int o = 16; o; o >>= 1) ss += __shfl_xor_sync(0xffffffffu, ss, o);
    if ((threadIdx.x & 31) == 0) red[threadIdx.x >> 5] = ss;
    __syncthreads();
    if (threadIdx.x < 32) {
        float v = (threadIdx.x < 4) ? red[threadIdx.x] : 0.0f;
        for (int o = 16; o; o >>= 1) v += __shfl_xor_sync(0xffffffffu, v, o);
        if (threadIdx.x == 0) red[0] = v;
    }
    __syncthreads();
    float rstd = rsqrtf(red[0] / (float)LL + 1e-6f);
    #pragma unroll
    for (int i = 0; i < 4; i++)
        p[threadIdx.x + i * 128] = __float2half_rn(vals[i] * rstd * w[threadIdx.x + i * 128]);
}

// both rope applications in one launch
__global__ void rope_both(__half* __restrict__ krope, __half* __restrict__ q,
                          const int* __restrict__ offset_p)
{
    const long per = (long)ROWS * HH * HALF_RD;
    long idx = (long)blockIdx.x * blockDim.x + threadIdx.x;
    __half* data; int ld, colbase;
    if (idx < per) { data = krope; ld = HH * RD; colbase = 0; }
    else if ((idx -= per) < per) { data = q; ld = QW; colbase = DOUT; }
    else return;
    int  j   = (int)(idx % HALF_RD);
    int  h   = (int)((idx / HALF_RD) % HH);
    long row = idx / (HALF_RD * HH);
    int  s   = (int)(row % SS);
    float pos = (float)(s + *offset_p);
    float inv = expf(-(float)j * (logf(10000.0f) / 32.0f));
    float ang = pos * inv;
    float c  = cosf(ang);
    float si = sinf(ang);
    __half* p = data + row * (long)ld + colbase + h * RD;
    float x1 = __half2float(p[j]), x2 = __half2float(p[j + HALF_RD]);
    p[j]           = __float2half_rn(x1 * c - x2 * si);
    p[j + HALF_RD] = __float2half_rn(x2 * c + x1 * si);
}

// masked scaled softmax; half scores in, half probs out; zero-fill to 128-grain
__global__ void __launch_bounds__(256)
softmax_kernel(const __half* __restrict__ scores, __half* __restrict__ probs,
               const int* __restrict__ offset_p)
{
    const long row = blockIdx.x;
    const int  s   = (int)(row % SS);
    const int  off = *offset_p;
    int valid = s + off + 1;
    if (valid > TT) valid = TT;
    int limit = ((s & ~127) + 128 + off + 127) & ~127;
    if (limit > TT) limit = TT;
    const __half* p = scores + row * (long)TT;
    __half* op = probs + row * (long)TT;
    const float scale = rsqrtf((float)(HD + RD));
    const int tid = threadIdx.x;
    const int e0 = tid * 8;

    float f[8];
    float m = -INFINITY;
    if (e0 < valid) {
        uint4 raw = *(const uint4*)(p + e0);
        const __half2* hp = (const __half2*)&raw;
        #pragma unroll
        for (int j = 0; j < 4; j++) {
            float2 v2 = __half22float2(hp[j]);
            f[j * 2]     = (e0 + j * 2 < valid)     ? v2.x * scale : -INFINITY;
            f[j * 2 + 1] = (e0 + j * 2 + 1 < valid) ? v2.y * scale : -INFINITY;
        }
        #pragma unroll
        for (int j = 0; j < 8; j++) m = fmaxf(m, f[j]);
    } else {
        #pragma unroll
        for (int j = 0; j < 8; j++) f[j] = -INFINITY;
    }

    __shared__ float red[32];
    for (int o = 16; o; o >>= 1) m = fmaxf(m, __shfl_xor_sync(0xffffffffu, m, o));
    if ((tid & 31) == 0) red[tid >> 5] = m;
    __syncthreads();
    if (tid < 32) {
        float t = (tid < 8) ? red[tid] : -INFINITY;
        for (int o = 16; o; o >>= 1) t = fmaxf(t, __shfl_xor_sync(0xffffffffu, t, o));
        if (tid == 0) red[0] = t;
    }
    __syncthreads();
    m = red[0];
    __syncthreads();

    float sum = 0.0f;
    #pragma unroll
    for (int j = 0; j < 8; j++) {
        float e = (f[j] == -INFINITY) ? 0.0f : expf(f[j] - m);
        f[j] = e;
        sum += e;
    }
    for (int o = 16; o; o >>= 1) sum += __shfl_xor_sync(0xffffffffu, sum, o);
    if ((tid & 31) == 0) red[tid >> 5] = sum;
    __syncthreads();
    if (tid < 32) {
        float t = (tid < 8) ? red[tid] : 0.0f;
        for (int o = 16; o; o >>= 1) t += __shfl_xor_sync(0xffffffffu, t, o);
        if (tid == 0) red[0] = t;
    }
    __syncthreads();
    float inv = 1.0f / red[0];

    if (e0 < limit) {
        uint4 outv;
        __half2* ho = (__half2*)&outv;
        #pragma unroll
        for (int j = 0; j < 4; j++)
            ho[j] = __floats2half2_rn(f[j * 2] * inv, f[j * 2 + 1] * inv);
        *(uint4*)(op + e0) = outv;
    }
}

// half->half 32x32 transpose, batched over z
__global__ void transpose_h(const __half* __restrict__ in, __half* __restrict__ out,
                            int R, int Cc, long sIn, long sOut)
{
    __shared__ __half t[32][33];
    const __half* ip = in + blockIdx.z * sIn;
    __half* op = out + blockIdx.z * sOut;
    const int c0 = blockIdx.x * 32, r0 = blockIdx.y * 32;
    for (int i = threadIdx.y; i < 32; i += 8)
        t[i][threadIdx.x] = ip[(long)(r0 + i) * Cc + c0 + threadIdx.x];
    __syncthreads();
    for (int i = threadIdx.y; i < 32; i += 8)
        op[(long)(c0 + i) * R + r0 + threadIdx.x] = t[threadIdx.x][i];
}

// ================= host side ====================================================
template<typename T>
static T* sym_addr(const void* sym)
{
    void* p = nullptr;
    cudaGetSymbolAddress(&p, sym);
    return (T*)p;
}

extern "C" void kernel_launch(void* const* d_in, const int* in_sizes, int n_in,
                              void* d_out, int out_size)
{
    const float* x       = (const float*)d_in[0];
    const float* W_DKV   = (const float*)d_in[1];
    const float* W_KRope = (const float*)d_in[2];
    const float* W_Q     = (const float*)d_in[3];
    const float* W_UK    = (const float*)d_in[4];
    const float* W_UV    = (const float*)d_in[5];
    const float* W_O     = (const float*)d_in[6];
    const float* kvw     = (const float*)d_in[7];
    const int*   offset  = (const int*)d_in[8];
    float* out = (float*)d_out;

    static int s_init = 0;
    if (!s_init) {
        cudaFuncSetAttribute((const void*)gemm_h<0>, cudaFuncAttributeMaxDynamicSharedMemorySize, GEMM_SMEM);
        cudaFuncSetAttribute((const void*)gemm_h<1>, cudaFuncAttributeMaxDynamicSharedMemorySize, GEMM_SMEM);
        cudaFuncSetAttribute((const void*)gemm_proj3, cudaFuncAttributeMaxDynamicSharedMemorySize, GEMM_SMEM);
        cudaFuncSetAttribute((const void*)gemm_scores, cudaFuncAttributeMaxDynamicSharedMemorySize, GEMM_SMEM);
        s_init = 1;
    }

    __half* x16    = sym_addr<__half>(g_x16);
    __half* wdkv16 = sym_addr<__half>(g_wdkv16);
    __half* wkr16  = sym_addr<__half>(g_wkr16);
    __half* wq16   = sym_addr<__half>(g_wq16);
    __half* wo16   = sym_addr<__half>(g_wo16);
    __half* wuv16  = sym_addr<__half>(g_wuv16);
    __half* wuk16  = sym_addr<__half>(g_wuk16);
    __half* ckv16  = sym_addr<__half>(g_ckv16);
    __half* ckvT16 = sym_addr<__half>(g_ckvT16);
    __half* krope16= sym_addr<__half>(g_krope16);
    __half* q16    = sym_addr<__half>(g_q16);
    __half* m2t16  = sym_addr<__half>(g_m2t16);
    __half* scores16 = sym_addr<__half>(g_scores16);
    __half* probs16  = sym_addr<__half>(g_probs16);
    __half* ctxlat16 = sym_addr<__half>(g_ctxlat16);
    __half* ctx16  = sym_addr<__half>(g_ctx16);

    // 0) half-round all seven fp32 inputs in ONE launch
    {
        const int nx = ROWS*DIN/4, n1 = LL*DIN/4, n2 = HH*RD*DIN/4;
        const int n3 = QW*DIN/4, n4 = DIN*DOUT/4, n5 = DOUT*LL/4, n6 = DOUT*LL/4;
        long total = (long)nx + n1 + n2 + n3 + n4 + n5 + n6;
        halfify_all<<<(int)((total + 255) / 256), 256>>>(
            x, x16, nx, W_DKV, wdkv16, n1, W_KRope, wkr16, n2,
            W_Q, wq16, n3, W_O, wo16, n4, W_UV, wuv16, n5, W_UK, wuk16, n6);
    }

    // 1-3) fused projections
    {
        dim3 grid(36, 32, 1);
        gemm_proj3<<<grid, 256, GEMM_SMEM>>>(x16, wdkv16, wkr16, wq16,
                                             ckv16, krope16, q16);
    }
    rmsnorm_kernel<<<ROWS, 128>>>(ckv16, kvw);
    {
        dim3 grid(LL / 32, SS / 32, BB), block(32, 8);
        transpose_h<<<grid, block>>>(ckv16, ckvT16, SS, LL,
                                     (long)SS * LL, (long)LL * SS);
    }
    {
        long total = 2L * ROWS * HH * HALF_RD;
        rope_both<<<(int)((total + 255) / 256), 256>>>(krope16, q16, offset);
    }

    // 4) M2T[b,h][t,d] = ckv[b][t,:] . W_UK[h][d,:]   (K=512, half out)
    {
        dim3 grid(HD / 128, TT / 128, BB * HH);
        gemm_h<1><<<grid, 256, GEMM_SMEM>>>(ckv16, wuk16, m2t16,
            LL, LL, LL, HD,
            HH,
            /*sAo(b)=*/(long)SS * LL, /*sAi(h)=*/0,
            /*sBo(b)=*/0,             /*sBi(h)=*/(long)HD * LL,
            /*sCo(b)=*/(long)HH * TT * HD, /*sCi(h)=*/(long)TT * HD,
            nullptr, 0);
    }

    // 5) fused scores: rope(K=64) + q_content @ M2T (K=128), causal skip
    {
        dim3 grid(TT / 128, SS / 128, BB * HH);
        gemm_scores<<<grid, 256, GEMM_SMEM>>>(q16, krope16, m2t16,
                                              scores16, offset);
    }

    // 6) softmax: half scores -> half probs
    softmax_kernel<<<BB * HH * SS, 256>>>(scores16, probs16, offset);

    // 7) ctx_lat = probs @ ckvT (K clipped causally), half out
    {
        dim3 grid(LL / 128, SS / 128, BB * HH);
        gemm_h<1><<<grid, 256, GEMM_SMEM>>>(probs16, ckvT16, ctxlat16,
            TT, TT, SS, HH * LL,
            HH, (long)HH * SS * TT, (long)SS * TT,
            (long)LL * SS, 0,
            (long)SS * HH * LL, LL, offset, 1);
    }

    // 8) ctx = ctxlat @ W_UV^T per head (fp16, half out)
    {
        dim3 grid(HD / 128, ROWS / 128, HH);
        gemm_h<1><<<grid, 256, GEMM_SMEM>>>(ctxlat16, wuv16, ctx16,
            LL, HH * LL, LL, DOUT,
            HH, 0, LL, 0, (long)HD * LL, 0, HD, nullptr, 0);
    }

    // 9) out = ctx @ W_O^T (fp32 out, staged coalesced)
    {
        dim3 grid(DIN / 128, ROWS / 128, 1);
        gemm_h<0><<<grid, 256, GEMM_SMEM>>>(ctx16, wo16, out,
            DOUT, DOUT, DOUT, DIN,
            1, 0, 0, 0, 0, 0, 0, nullptr, 0);
    }
}

// round 15
// speedup vs baseline: 1.9885x; 1.2060x over previous
#include <cuda_runtime.h>
#include <cuda_fp16.h>
#include <math.h>
#include <stdint.h>

// Problem constants
#define BB 2
#define SS 2048
#define TT 2048
#define DIN 2048
#define DOUT 2048
#define HH 16
#define RD 64
#define HALF_RD 32
#define LL 512
#define HD 128
#define ROWS (BB*SS)          // 4096
#define QW (DOUT+HH*RD)       // 3072

// ---------------- device scratch (static; no allocations) ---------------------
__device__ __align__(128) __half g_x16  [ROWS*DIN];
__device__ __align__(128) __half g_wdkv16[LL*DIN];
__device__ __align__(128) __half g_wkr16 [HH*RD*DIN];
__device__ __align__(128) __half g_wq16  [QW*DIN];
__device__ __align__(128) __half g_wo16  [DIN*DOUT];
__device__ __align__(128) __half g_wuv16 [DOUT*LL];
__device__ __align__(128) __half g_wuk16 [DOUT*LL];
__device__ __align__(128) __half g_ckv16 [BB*SS*LL];
__device__ __align__(128) __half g_vt16  [(long)BB*DOUT*SS];    // [b][i, t]
__device__ __align__(128) __half g_krope16[BB*SS*HH*RD];
__device__ __align__(128) __half g_q16   [BB*SS*QW];
__device__ __align__(128) __half g_m2t16 [(long)BB*HH*TT*HD];   // [b,h][t,d]
__device__ __align__(128) __half g_scores16[(long)BB*HH*SS*TT];
__device__ __align__(128) __half g_probs16 [(long)BB*HH*SS*TT];
__device__ __align__(128) __half g_ctx16 [ROWS*DOUT];

// ================= helpers =====================================================
__device__ __forceinline__ uint32_t smem_u32(const void* p) {
    uint32_t a;
    asm("{ .reg .u64 t; cvta.to.shared.u64 t, %1; cvt.u32.u64 %0, t; }" : "=r"(a) : "l"(p));
    return a;
}
__device__ __forceinline__ void cp16(uint32_t dst, const void* src) {
    asm volatile("cp.async.cg.shared.global [%0], [%1], 16;" :: "r"(dst), "l"(src));
}
#define CP_COMMIT() asm volatile("cp.async.commit_group;" ::: "memory")
#define CP_WAIT1()  asm volatile("cp.async.wait_group 1;"  ::: "memory")
#define CP_WAIT0()  asm volatile("cp.async.wait_group 0;"  ::: "memory")

__device__ __forceinline__ void ldsm4(uint32_t* r, uint32_t addr) {
    asm volatile("ldmatrix.sync.aligned.m8n8.x4.shared.b16 {%0,%1,%2,%3}, [%4];"
                 : "=r"(r[0]), "=r"(r[1]), "=r"(r[2]), "=r"(r[3]) : "r"(addr));
}
__device__ __forceinline__ void mma_f16(float* c, const uint32_t* a, const uint32_t* b) {
    asm volatile(
        "mma.sync.aligned.m16n8k16.row.col.f32.f16.f16.f32 "
        "{%0,%1,%2,%3}, {%4,%5,%6,%7}, {%8,%9}, {%0,%1,%2,%3};"
        : "+f"(c[0]), "+f"(c[1]), "+f"(c[2]), "+f"(c[3])
        : "r"(a[0]), "r"(a[1]), "r"(a[2]), "r"(a[3]), "r"(b[0]), "r"(b[1]));
}

// ================= FP16 GEMM tile engine: 128x128, K-chunk 64, 3 stages =========
#define STGB 36864
#define GEMM_SMEM (3*STGB)      // 110592 B; x2 CTA = 216 KB <= 228 KB

__device__ __forceinline__ void gemm_tiles_h(
    const __half* __restrict__ A, const __half* __restrict__ B,
    int K, int lda, int ldb, float (*acc)[4][4], char* sm)
{
    const int tid  = threadIdx.x;
    const int lane = tid & 31;
    const int wid  = tid >> 5;
    const int wm   = wid >> 2;
    const int wn   = wid & 3;

    const uint32_t sbase = smem_u32(sm);

    const int aRow = wm * 64 + (lane & 7) + ((lane >> 3) & 1) * 8;
    const uint32_t aOff = (uint32_t)(aRow * 72 + ((lane >> 4) & 1) * 8) * 2;
    const int bRow = wn * 32 + (lane & 7) + ((lane >> 4) & 1) * 8;
    const uint32_t bOff = (uint32_t)(bRow * 72 + ((lane >> 3) & 1) * 8) * 2;

    auto issue = [&](int c) {
        const int k0 = c << 6;
        const uint32_t st = sbase + (uint32_t)(c % 3) * STGB;
        #pragma unroll
        for (int i = 0; i < 4; i++) {
            int op = tid + i * 256;
            int row = op >> 3, c8 = (op & 7) * 8;
            uint32_t d = st + (uint32_t)(row * 72 + c8) * 2;
            cp16(d,           A + (long)row * lda + k0 + c8);
            cp16(d + 18432,   B + (long)row * ldb + k0 + c8);
        }
    };

    auto compute = [&](int c) {
        const uint32_t As = sbase + (uint32_t)(c % 3) * STGB;
        const uint32_t Bs = As + 18432;
        #pragma unroll
        for (int ks = 0; ks < 4; ks++) {
            uint32_t ah[4][4], bh[4][2];
            #pragma unroll
            for (int mt = 0; mt < 4; mt++)
                ldsm4(ah[mt], As + aOff + (uint32_t)(mt * 16 * 72 + ks * 16) * 2);
            #pragma unroll
            for (int np = 0; np < 2; np++) {
                uint32_t raw[4];
                ldsm4(raw, Bs + bOff + (uint32_t)(np * 16 * 72 + ks * 16) * 2);
                bh[np * 2][0] = raw[0]; bh[np * 2][1] = raw[1];
                bh[np * 2 + 1][0] = raw[2]; bh[np * 2 + 1][1] = raw[3];
            }
            #pragma unroll
            for (int mt = 0; mt < 4; mt++)
                #pragma unroll
                for (int nt = 0; nt < 4; nt++)
                    mma_f16(acc[mt][nt], ah[mt], bh[nt]);
        }
    };

    const int NC = K >> 6;
    issue(0); CP_COMMIT();
    if (1 < NC) issue(1);
    CP_COMMIT();
    for (int c = 0; c < NC; c++) {
        CP_WAIT1();
        __syncthreads();
        if (c + 2 < NC) issue(c + 2);
        CP_COMMIT();
        compute(c);
    }
    CP_WAIT0();
    __syncthreads();
}

// ======= staged epilogue: acc -> SMEM -> coalesced 16B GMEM stores =============
template<int OUTH>
__device__ __forceinline__ void gemm_epi(
    void* __restrict__ Cv, int ldc, int m0, int n0, float (*acc)[4][4], char* sm)
{
    const int tid  = threadIdx.x;
    const int lane = tid & 31;
    const int wid  = tid >> 5;
    const int gid  = lane >> 2;
    const int tig  = lane & 3;
    const int wm   = wid >> 2;
    const int wn   = wid & 3;

    if (OUTH) {
        __half* ts = (__half*)sm;
        #pragma unroll
        for (int mt = 0; mt < 4; mt++) {
            #pragma unroll
            for (int nt = 0; nt < 4; nt++) {
                int r  = wm * 64 + mt * 16 + gid;
                int cc = wn * 32 + nt * 8 + tig * 2;
                *(__half2*)&ts[r * 136 + cc] =
                    __floats2half2_rn(acc[mt][nt][0], acc[mt][nt][1]);
                *(__half2*)&ts[(r + 8) * 136 + cc] =
                    __floats2half2_rn(acc[mt][nt][2], acc[mt][nt][3]);
            }
        }
        __syncthreads();
        __half* C = (__half*)Cv + (long)m0 * ldc + n0;
        #pragma unroll
        for (int i = 0; i < 8; i++) {
            int idx = tid + i * 256;
            int row = idx >> 4, c16 = idx & 15;
            uint4 v = *(const uint4*)&ts[row * 136 + c16 * 8];
            *(uint4*)&C[(long)row * ldc + c16 * 8] = v;
        }
    } else {
        float* ts = (float*)sm;
        #pragma unroll
        for (int mt = 0; mt < 4; mt++) {
            #pragma unroll
            for (int nt = 0; nt < 4; nt++) {
                int r  = wm * 64 + mt * 16 + gid;
                int cc = wn * 32 + nt * 8 + tig * 2;
                *(float2*)&ts[r * 132 + cc] =
                    make_float2(acc[mt][nt][0], acc[mt][nt][1]);
                *(float2*)&ts[(r + 8) * 132 + cc] =
                    make_float2(acc[mt][nt][2], acc[mt][nt][3]);
            }
        }
        __syncthreads();
        float* C = (float*)Cv + (long)m0 * ldc + n0;
        #pragma unroll
        for (int i = 0; i < 16; i++) {
            int idx = tid + i * 256;
            int row = idx >> 5, c4 = idx & 31;
            uint4 v = *(const uint4*)&ts[row * 132 + c4 * 4];
            *(uint4*)&C[(long)row * ldc + c4 * 4] = v;
        }
    }
    __syncthreads();
}

#define ACC_INIT(acc) { _Pragma("unroll") for (int _m = 0; _m < 4; _m++) \
    _Pragma("unroll") for (int _n = 0; _n < 4; _n++) \
    _Pragma("unroll") for (int _i = 0; _i < 4; _i++) acc[_m][_n][_i] = 0.0f; }

// generic batched fp16 GEMM; kclip limits K causally (128-grain, mult of 64)
template<int OUTH>
__global__ void __launch_bounds__(256, 2)
gemm_h(const __half* __restrict__ Ab, const __half* __restrict__ Bb, void* __restrict__ Cb,
       int K, int lda, int ldb, int ldc,
       int zInner, long sAo, long sAi, long sBo, long sBi, long sCo, long sCi,
       const int* offset_p, int kclip)
{
    extern __shared__ char smc[];
    const int z  = blockIdx.z;
    const int zo = z / zInner, zi = z % zInner;
    const int m0 = blockIdx.y * 128;
    const int n0 = blockIdx.x * 128;
    if (kclip) {
        int lim = m0 + 128 + *offset_p;
        lim = (lim + 127) & ~127;
        if (lim < K) K = lim;
    }
    float acc[4][4][4];
    ACC_INIT(acc);
    gemm_tiles_h(Ab + zo * sAo + zi * sAi + (long)m0 * lda,
                 Bb + zo * sBo + zi * sBi + (long)n0 * ldb,
                 K, lda, ldb, acc, smc);
    if (OUTH)
        gemm_epi<1>((__half*)Cb + zo * sCo + zi * sCi, ldc, m0, n0, acc, smc);
    else
        gemm_epi<0>((float*)Cb + zo * sCo + zi * sCi, ldc, m0, n0, acc, smc);
}

// fused triple projection (half out): ckv 4 | krope 8 | q 24 blocks of 128
__global__ void __launch_bounds__(256, 2)
gemm_proj3(const __half* __restrict__ x,
           const __half* __restrict__ Wdkv, const __half* __restrict__ Wkr,
           const __half* __restrict__ Wq,
           __half* __restrict__ ckv, __half* __restrict__ krope, __half* __restrict__ q)
{
    extern __shared__ char smc[];
    const int bx = blockIdx.x;
    const __half* B; __half* C; int ldc, n0;
    if (bx < 4)       { B = Wdkv; C = ckv;   ldc = LL;       n0 = bx * 128; }
    else if (bx < 12) { B = Wkr;  C = krope; ldc = HH * RD;  n0 = (bx - 4) * 128; }
    else              { B = Wq;   C = q;     ldc = QW;       n0 = (bx - 12) * 128; }
    const int m0 = blockIdx.y * 128;
    float acc[4][4][4];
    ACC_INIT(acc);
    gemm_tiles_h(x + (long)m0 * DIN, B + (long)n0 * DIN, DIN, DIN, DIN, acc, smc);
    gemm_epi<1>(C, ldc, m0, n0, acc, smc);
}

// fused scores: rope (K=64) + absorbed latent (K=128 via M2T), causal skip
__global__ void __launch_bounds__(256, 2)
gemm_scores(const __half* __restrict__ q, const __half* __restrict__ krope,
            const __half* __restrict__ m2t,
            __half* __restrict__ scores, const int* __restrict__ offset_p)
{
    extern __shared__ char smc[];
    const int m0 = blockIdx.y * 128;
    const int n0 = blockIdx.x * 128;
    if (n0 > m0 + 127 + *offset_p) return;
    const int b = blockIdx.z >> 4;
    const int h = blockIdx.z & 15;

    float acc[4][4][4];
    ACC_INIT(acc);

    const __half* A1 = q + (long)b * SS * QW + DOUT + h * RD + (long)m0 * QW;
    const __half* B1 = krope + (long)b * SS * (HH * RD) + h * RD + (long)n0 * (HH * RD);
    gemm_tiles_h(A1, B1, RD, QW, HH * RD, acc, smc);

    const __half* A2 = q + (long)b * SS * QW + h * HD + (long)m0 * QW;
    const __half* B2 = m2t + (long)blockIdx.z * TT * HD + (long)n0 * HD;
    gemm_tiles_h(A2, B2, HD, QW, HD, acc, smc);

    gemm_epi<1>(scores + (long)blockIdx.z * SS * TT, TT, m0, n0, acc, smc);
}

// ================= small kernels ===============================================
// one kernel, seven fp32->fp16 segments (float4 granularity)
__global__ void halfify_all(
    const float* s0, __half* d0, int n0,
    const float* s1, __half* d1, int n1,
    const float* s2, __half* d2, int n2,
    const float* s3, __half* d3, int n3,
    const float* s4, __half* d4, int n4,
    const float* s5, __half* d5, int n5,
    const float* s6, __half* d6, int n6)
{
    long i = (long)blockIdx.x * blockDim.x + threadIdx.x;
    const float* s; __half* d;
    if (i < n0)              { s = s0; d = d0; }
    else if ((i -= n0) < n1) { s = s1; d = d1; }
    else if ((i -= n1) < n2) { s = s2; d = d2; }
    else if ((i -= n2) < n3) { s = s3; d = d3; }
    else if ((i -= n3) < n4) { s = s4; d = d4; }
    else if ((i -= n4) < n5) { s = s5; d = d5; }
    else if ((i -= n5) < n6) { s = s6; d = d6; }
    else return;
    float4 v = ((const float4*)s)[i];
    __half2* o = (__half2*)d;
    o[i * 2]     = __floats2half2_rn(v.x, v.y);
    o[i * 2 + 1] = __floats2half2_rn(v.z, v.w);
}

__global__ void rmsnorm_kernel(__half* __restrict__ data, const float* __restrict__ w)
{
    const int row = blockIdx.x;
    __half* p = data + (long)row * LL;
    float ss = 0.0f;
    float vals[4];
    #pragma unroll
    for (int i = 0; i < 4; i++) {
        vals[i] = __half2float(p[threadIdx.x + i * 128]);
        ss += vals[i] * vals[i];
    }
    __shared__ float red[32];
    for (int o = 16; o; o >>= 1) ss += __shfl_xor_sync(0xffffffffu, ss, o);
    if ((threadIdx.x & 31) == 0) red[threadIdx.x >> 5] = ss;
    __syncthreads();
    if (threadIdx.x < 32) {
        float v = (threadIdx.x < 4) ? red[threadIdx.x] : 0.0f;
        for (int o = 16; o; o >>= 1) v += __shfl_xor_sync(0xffffffffu, v, o);
        if (threadIdx.x == 0) red[0] = v;
    }
    __syncthreads();
    float rstd = rsqrtf(red[0] / (float)LL + 1e-6f);
    #pragma unroll
    for (int i = 0; i < 4; i++)
        p[threadIdx.x + i * 128] = __float2half_rn(vals[i] * rstd * w[threadIdx.x + i * 128]);
}

// both rope applications in one launch
__global__ void rope_both(__half* __restrict__ krope, __half* __restrict__ q,
                          const int* __restrict__ offset_p)
{
    const long per = (long)ROWS * HH * HALF_RD;
    long idx = (long)blockIdx.x * blockDim.x + threadIdx.x;
    __half* data; int ld, colbase;
    if (idx < per) { data = krope; ld = HH * RD; colbase = 0; }
    else if ((idx -= per) < per) { data = q; ld = QW; colbase = DOUT; }
    else return;
    int  j   = (int)(idx % HALF_RD);
    int  h   = (int)((idx / HALF_RD) % HH);
    long row = idx / (HALF_RD * HH);
    int  s   = (int)(row % SS);
    float pos = (float)(s + *offset_p);
    float inv = expf(-(float)j * (logf(10000.0f) / 32.0f));
    float ang = pos * inv;
    float c  = cosf(ang);
    float si = sinf(ang);
    __half* p = data + row * (long)ld + colbase + h * RD;
    float x1 = __half2float(p[j]), x2 = __half2float(p[j + HALF_RD]);
    p[j]           = __float2half_rn(x1 * c - x2 * si);
    p[j + HALF_RD] = __float2half_rn(x2 * c + x1 * si);
}

// masked scaled softmax; half scores in, half probs out; zero-fill to 128-grain
__global__ void __launch_bounds__(256)
softmax_kernel(const __half* __restrict__ scores, __half* __restrict__ probs,
               const int* __restrict__ offset_p)
{
    const long row = blockIdx.x;
    const int  s   = (int)(row % SS);
    const int  off = *offset_p;
    int valid = s + off + 1;
    if (valid > TT) valid = TT;
    int limit = ((s & ~127) + 128 + off + 127) & ~127;
    if (limit > TT) limit = TT;
    const __half* p = scores + row * (long)TT;
    __half* op = probs + row * (long)TT;
    const float scale = rsqrtf((float)(HD + RD));
    const int tid = threadIdx.x;
    const int e0 = tid * 8;

    float f[8];
    float m = -INFINITY;
    if (e0 < valid) {
        uint4 raw = *(const uint4*)(p + e0);
        const __half2* hp = (const __half2*)&raw;
        #pragma unroll
        for (int j = 0; j < 4; j++) {
            float2 v2 = __half22float2(hp[j]);
            f[j * 2]     = (e0 + j * 2 < valid)     ? v2.x * scale : -INFINITY;
            f[j * 2 + 1] = (e0 + j * 2 + 1 < valid) ? v2.y * scale : -INFINITY;
        }
        #pragma unroll
        for (int j = 0; j < 8; j++) m = fmaxf(m, f[j]);
    } else {
        #pragma unroll
        for (int j = 0; j < 8; j++) f[j] = -INFINITY;
    }

    __shared__ float red[32];
    for (int o = 16; o; o >>= 1) m = fmaxf(m, __shfl_xor_sync(0xffffffffu, m, o));
    if ((tid & 31) == 0) red[tid >> 5] = m;
    __syncthreads();
    if (tid < 32) {
        float t = (tid < 8) ? red[tid] : -INFINITY;
        for (int o = 16; o; o >>= 1) t = fmaxf(t, __shfl_xor_sync(0xffffffffu, t, o));
        if (tid == 0) red[0] = t;
    }
    __syncthreads();
    m = red[0];
    __syncthreads();

    float sum = 0.0f;
    #pragma unroll
    for (int j = 0; j < 8; j++) {
        float e = (f[j] == -INFINITY) ? 0.0f : expf(f[j] - m);
        f[j] = e;
        sum += e;
    }
    for (int o = 16; o; o >>= 1) sum += __shfl_xor_sync(0xffffffffu, sum, o);
    if ((tid & 31) == 0) red[tid >> 5] = sum;
    __syncthreads();
    if (tid < 32) {
        float t = (tid < 8) ? red[tid] : 0.0f;
        for (int o = 16; o; o >>= 1) t += __shfl_xor_sync(0xffffffffu, t, o);
        if (tid == 0) red[0] = t;
    }
    __syncthreads();
    float inv = 1.0f / red[0];

    if (e0 < limit) {
        uint4 outv;
        __half2* ho = (__half2*)&outv;
        #pragma unroll
        for (int j = 0; j < 4; j++)
            ho[j] = __floats2half2_rn(f[j * 2] * inv, f[j * 2 + 1] * inv);
        *(uint4*)(op + e0) = outv;
    }
}

// ================= host side ====================================================
template<typename T>
static T* sym_addr(const void* sym)
{
    void* p = nullptr;
    cudaGetSymbolAddress(&p, sym);
    return (T*)p;
}

extern "C" void kernel_launch(void* const* d_in, const int* in_sizes, int n_in,
                              void* d_out, int out_size)
{
    const float* x       = (const float*)d_in[0];
    const float* W_DKV   = (const float*)d_in[1];
    const float* W_KRope = (const float*)d_in[2];
    const float* W_Q     = (const float*)d_in[3];
    const float* W_UK    = (const float*)d_in[4];
    const float* W_UV    = (const float*)d_in[5];
    const float* W_O     = (const float*)d_in[6];
    const float* kvw     = (const float*)d_in[7];
    const int*   offset  = (const int*)d_in[8];
    float* out = (float*)d_out;

    static int s_init = 0;
    if (!s_init) {
        cudaFuncSetAttribute((const void*)gemm_h<0>, cudaFuncAttributeMaxDynamicSharedMemorySize, GEMM_SMEM);
        cudaFuncSetAttribute((const void*)gemm_h<1>, cudaFuncAttributeMaxDynamicSharedMemorySize, GEMM_SMEM);
        cudaFuncSetAttribute((const void*)gemm_proj3, cudaFuncAttributeMaxDynamicSharedMemorySize, GEMM_SMEM);
        cudaFuncSetAttribute((const void*)gemm_scores, cudaFuncAttributeMaxDynamicSharedMemorySize, GEMM_SMEM);
        s_init = 1;
    }

    __half* x16    = sym_addr<__half>(g_x16);
    __half* wdkv16 = sym_addr<__half>(g_wdkv16);
    __half* wkr16  = sym_addr<__half>(g_wkr16);
    __half* wq16   = sym_addr<__half>(g_wq16);
    __half* wo16   = sym_addr<__half>(g_wo16);
    __half* wuv16  = sym_addr<__half>(g_wuv16);
    __half* wuk16  = sym_addr<__half>(g_wuk16);
    __half* ckv16  = sym_addr<__half>(g_ckv16);
    __half* vt16   = sym_addr<__half>(g_vt16);
    __half* krope16= sym_addr<__half>(g_krope16);
    __half* q16    = sym_addr<__half>(g_q16);
    __half* m2t16  = sym_addr<__half>(g_m2t16);
    __half* scores16 = sym_addr<__half>(g_scores16);
    __half* probs16  = sym_addr<__half>(g_probs16);
    __half* ctx16  = sym_addr<__half>(g_ctx16);

    // 0) half-round all seven fp32 inputs in ONE launch
    {
        const int nx = ROWS*DIN/4, n1 = LL*DIN/4, n2 = HH*RD*DIN/4;
        const int n3 = QW*DIN/4, n4 = DIN*DOUT/4, n5 = DOUT*LL/4, n6 = DOUT*LL/4;
        long total = (long)nx + n1 + n2 + n3 + n4 + n5 + n6;
        halfify_all<<<(int)((total + 255) / 256), 256>>>(
            x, x16, nx, W_DKV, wdkv16, n1, W_KRope, wkr16, n2,
            W_Q, wq16, n3, W_O, wo16, n4, W_UV, wuv16, n5, W_UK, wuk16, n6);
    }

    // 1-3) fused projections
    {
        dim3 grid(36, 32, 1);
        gemm_proj3<<<grid, 256, GEMM_SMEM>>>(x16, wdkv16, wkr16, wq16,
                                             ckv16, krope16, q16);
    }
    rmsnorm_kernel<<<ROWS, 128>>>(ckv16, kvw);
    {
        long total = 2L * ROWS * HH * HALF_RD;
        rope_both<<<(int)((total + 255) / 256), 256>>>(krope16, q16, offset);
    }

    // 4a) M2T[b,h][t,d] = ckv[b][t,:] . W_UK[h][d,:]   (K=512)
    {
        dim3 grid(HD / 128, TT / 128, BB * HH);
        gemm_h<1><<<grid, 256, GEMM_SMEM>>>(ckv16, wuk16, m2t16,
            LL, LL, LL, HD,
            HH,
            (long)SS * LL, 0,
            0, (long)HD * LL,
            (long)HH * TT * HD, (long)TT * HD,
            nullptr, 0);
    }

    // 4b) VT[b][i,t] = W_UV[i,:] . ckv[b][t,:]   (K=512, replaces ckv transpose)
    {
        dim3 grid(SS / 128, DOUT / 128, BB);
        gemm_h<1><<<grid, 256, GEMM_SMEM>>>(wuv16, ckv16, vt16,
            LL, LL, LL, SS,
            1,
            0, 0,
            (long)SS * LL, 0,
            (long)DOUT * SS, 0,
            nullptr, 0);
    }

    // 5) fused scores: rope(K=64) + q_content @ M2T (K=128), causal skip
    {
        dim3 grid(TT / 128, SS / 128, BB * HH);
        gemm_scores<<<grid, 256, GEMM_SMEM>>>(q16, krope16, m2t16,
                                              scores16, offset);
    }

    // 6) softmax: half scores -> half probs
    softmax_kernel<<<BB * HH * SS, 256>>>(scores16, probs16, offset);

    // 7) ctx = probs @ VT^T per head (K=T clipped causally), half out
    //    ctx[b*SS+s, h*HD+d] = sum_t probs[b,h][s,t] * VT[b][h*HD+d, t]
    {
        dim3 grid(HD / 128, SS / 128, BB * HH);
        gemm_h<1><<<grid, 256, GEMM_SMEM>>>(probs16, vt16, ctx16,
            TT, TT, SS, DOUT,
            HH,
            (long)HH * SS * TT, (long)SS * TT,
            (long)DOUT * SS, (long)HD * SS,
            (long)SS * DOUT, HD,
            offset, 1);
    }

    // 8) out = ctx @ W_O^T (fp32 out, staged coalesced)
    {
        dim3 grid(DIN / 128, ROWS / 128, 1);
        gemm_h<0><<<grid, 256, GEMM_SMEM>>>(ctx16, wo16, out,
            DOUT, DOUT, DOUT, DIN,
            1, 0, 0, 0, 0, 0, 0, nullptr, 0);
    }
}